// round 1
// baseline (speedup 1.0000x reference)
#include <cuda_runtime.h>
#include <math.h>

// Problem constants
#define BB 8
#define NN 2048
#define FF 128
#define MI 64            // i-rows per block in main kernel
#define TJ 64            // j-tile width
#define NTILES (NN / TJ) // 32
#define ITILES (NN / MI) // 32

typedef unsigned long long ull;

// -------- device scratch (no allocations allowed in kernel_launch) --------
__device__ float g_Wh[BB * NN * FF];   // 8 MB
__device__ float g_wa[2 * FF];         // W@a1, W@a2
__device__ float g_f1[BB * NN];
__device__ float g_f2[BB * NN];
__device__ float g_E1p[BB * NN];       // exp(f1)
__device__ float g_E1n[BB * NN];       // exp(0.2 f1)
__device__ float g_E2p[BB * NN];       // exp(f2)
__device__ float g_E2n[BB * NN];       // exp(0.2 f2)

// -------- packed f32x2 helpers (Blackwell FFMA2) --------
__device__ __forceinline__ ull pk2(float lo, float hi) {
    ull d;
    asm("mov.b64 %0, {%1, %2};" : "=l"(d)
        : "r"(__float_as_uint(lo)), "r"(__float_as_uint(hi)));
    return d;
}
__device__ __forceinline__ void upk2(ull v, float& lo, float& hi) {
    unsigned a, b;
    asm("mov.b64 {%0, %1}, %2;" : "=r"(a), "=r"(b) : "l"(v));
    lo = __uint_as_float(a);
    hi = __uint_as_float(b);
}
__device__ __forceinline__ ull pfma(ull a, ull b, ull c) {
    ull d;
    asm("fma.rn.f32x2 %0, %1, %2, %3;" : "=l"(d) : "l"(a), "l"(b), "l"(c));
    return d;
}

// ===================== k0: wa = W @ a1, W @ a2  (1 block) =====================
__global__ void k0_wa(const float* __restrict__ W, const float* __restrict__ a) {
    int f = threadIdx.x;  // 0..127
    float s1 = 0.f, s2 = 0.f;
    #pragma unroll 8
    for (int o = 0; o < FF; o++) {
        float w = W[f * FF + o];
        s1 += w * a[o];
        s2 += w * a[FF + o];
    }
    g_wa[f] = s1;
    g_wa[FF + f] = s2;
}

// ===================== k1: Wh = h @ W  (tiled GEMM, packed FMA) ==============
// grid = 256 blocks (64 rows each), 256 threads
__global__ __launch_bounds__(256, 2) void k1_gemm(const float* __restrict__ h,
                                                  const float* __restrict__ W) {
    extern __shared__ char smem1[];
    float* Ws = (float*)smem1;            // 128x128 = 64KB
    float* hs = (float*)(smem1 + 65536);  // 64x128  = 32KB

    int tid = threadIdx.x;
    const float* hb = h + (size_t)blockIdx.x * MI * FF;

    #pragma unroll
    for (int i = tid * 4; i < FF * FF; i += 1024)
        *(float4*)&Ws[i] = *(const float4*)&W[i];
    #pragma unroll
    for (int i = tid * 4; i < MI * FF; i += 1024)
        *(float4*)&hs[i] = *(const float4*)&hb[i];
    __syncthreads();

    int c0 = (tid & 31) * 4;  // 4 output cols per lane
    int r0 = (tid >> 5) * 8;  // 8 rows per warp-group
    ull accA[8], accB[8];
    #pragma unroll
    for (int r = 0; r < 8; r++) { accA[r] = 0ULL; accB[r] = 0ULL; }

    for (int k = 0; k < FF; k++) {
        float4 w = *(float4*)&Ws[k * FF + c0];
        ull wA = pk2(w.x, w.y);
        ull wB = pk2(w.z, w.w);
        #pragma unroll
        for (int r = 0; r < 8; r++) {
            float hv = hs[(r0 + r) * FF + k];  // broadcast LDS
            ull hd = pk2(hv, hv);
            accA[r] = pfma(hd, wA, accA[r]);
            accB[r] = pfma(hd, wB, accB[r]);
        }
    }

    float* out = g_Wh + (size_t)blockIdx.x * MI * FF;
    #pragma unroll
    for (int r = 0; r < 8; r++) {
        float4 o;
        upk2(accA[r], o.x, o.y);
        upk2(accB[r], o.z, o.w);
        *(float4*)&out[(r0 + r) * FF + c0] = o;
    }
}

// ===================== k2: f1,f2 + exp tables (one warp per row) =============
__global__ void k2_scores(const float* __restrict__ h) {
    int row = blockIdx.x * 8 + (threadIdx.x >> 5);  // 0..16383
    int lane = threadIdx.x & 31;
    float s1 = 0.f, s2 = 0.f;
    #pragma unroll
    for (int q = 0; q < 4; q++) {
        float hv = h[(size_t)row * FF + lane + 32 * q];
        s1 += hv * g_wa[lane + 32 * q];
        s2 += hv * g_wa[FF + lane + 32 * q];
    }
    #pragma unroll
    for (int o = 16; o; o >>= 1) {
        s1 += __shfl_xor_sync(0xFFFFFFFFu, s1, o);
        s2 += __shfl_xor_sync(0xFFFFFFFFu, s2, o);
    }
    if (lane == 0) {
        g_f1[row]  = s1;
        g_f2[row]  = s2;
        g_E1p[row] = expf(s1);
        g_E1n[row] = expf(0.2f * s1);
        g_E2p[row] = expf(s2);
        g_E2n[row] = expf(0.2f * s2);
    }
}

// ===================== k3: fused masked-softmax aggregation ==================
// grid = (ITILES, BB), 256 threads; dynamic smem ~67KB -> 2 blocks/SM
__global__ __launch_bounds__(256, 2) void k3_main(const float* __restrict__ adj,
                                                  const float* __restrict__ bias,
                                                  float* __restrict__ out) {
    extern __shared__ char smem3[];
    float*  Wh_s = (float*)smem3;                        // [TJ][FF]    32768 B
    float2* u_s  = (float2*)(smem3 + 32768);             // [MI][TJ+1]  33280 B (padded)
    float*  f2_s = (float*)(smem3 + 32768 + 33280);      // [TJ]
    float*  E2p_s = f2_s + TJ;
    float*  E2n_s = f2_s + 2 * TJ;
    float*  zfin  = f2_s + 3 * TJ;                       // [MI]

    const int tid = threadIdx.x;
    const int b = blockIdx.y;
    const int i0 = blockIdx.x * MI;
    const int bn = b * NN;

    // phase-1 identity: thread -> (row, 16 cols in 4 strided float4 chunks)
    const int p_row = tid >> 2;            // 0..63
    const int p_cb  = (tid & 3) * 4;       // col base within 16-block
    const float rf1  = g_f1[bn + i0 + p_row];
    const float rE1p = g_E1p[bn + i0 + p_row];
    const float rE1n = g_E1n[bn + i0 + p_row];
    float z_part = 0.f;
    const float* adj_row = adj + (size_t)(i0 + p_row) * NN;

    // phase-2 identity: warp -> 8 rows, lane -> 4 features
    const int warp = tid >> 5, lane = tid & 31;
    const int r0 = warp * 8;
    const int c0 = lane * 4;
    const float* Whb = g_Wh + (size_t)bn * FF;

    ull accA[8], accB[8];
    #pragma unroll
    for (int r = 0; r < 8; r++) { accA[r] = 0ULL; accB[r] = 0ULL; }

    for (int t = 0; t < NTILES; t++) {
        const int jb = t * TJ;
        __syncthreads();  // protect smem reuse from previous tile's readers

        // ---- phase 0: stage Wh tile + per-col score tables ----
        const float* src = Whb + (size_t)jb * FF;
        #pragma unroll
        for (int i = tid * 4; i < TJ * FF; i += 1024)
            *(float4*)&Wh_s[i] = *(const float4*)&src[i];
        if (tid < TJ)               f2_s[tid]            = g_f2[bn + jb + tid];
        else if (tid < 2 * TJ)      E2p_s[tid - TJ]      = g_E2p[bn + jb + tid - TJ];
        else if (tid < 3 * TJ)      E2n_s[tid - 2 * TJ]  = g_E2n[bn + jb + tid - 2 * TJ];
        __syncthreads();

        // ---- phase 1: masked unnormalized weights u (pre-duplicated f32x2) ----
        #pragma unroll
        for (int q = 0; q < 4; q++) {
            const int cb = p_cb + q * 16;
            float4 av = *(const float4*)&adj_row[jb + cb];
            #pragma unroll
            for (int e = 0; e < 4; e++) {
                const int c = cb + e;
                const float am = (&av.x)[e];
                const float s = rf1 + f2_s[c];
                float u = (s > 0.f) ? (rE1p * E2p_s[c]) : (rE1n * E2n_s[c]);
                u = (am > 0.f) ? u : 0.f;
                z_part += u;
                u_s[p_row * (TJ + 1) + c] = make_float2(u, u);
            }
        }
        __syncthreads();

        // ---- phase 2: acc[r][f] += u[r][j] * Wh[j][f]  (packed FMA) ----
        for (int jj = 0; jj < TJ; jj += 4) {
            ull wA[4], wB[4];
            #pragma unroll
            for (int jo = 0; jo < 4; jo++) {
                float4 w = *(float4*)&Wh_s[(jj + jo) * FF + c0];
                wA[jo] = pk2(w.x, w.y);
                wB[jo] = pk2(w.z, w.w);
            }
            #pragma unroll
            for (int r = 0; r < 8; r++) {
                const float2* up = &u_s[(r0 + r) * (TJ + 1) + jj];
                #pragma unroll
                for (int jo = 0; jo < 4; jo++) {
                    ull ud = *(const ull*)&up[jo];  // LDS.64 broadcast, (u,u)
                    accA[r] = pfma(ud, wA[jo], accA[r]);
                    accB[r] = pfma(ud, wB[jo], accB[r]);
                }
            }
        }
    }

    // ---- Z reduction: 4 threads per row (adjacent lanes) ----
    float z = z_part;
    z += __shfl_xor_sync(0xFFFFFFFFu, z, 1);
    z += __shfl_xor_sync(0xFFFFFFFFu, z, 2);
    if ((tid & 3) == 0) zfin[p_row] = z;
    __syncthreads();

    // ---- phase 3: divide by Z, +bias, ELU, store ----
    const float b0 = bias[c0], b1 = bias[c0 + 1], b2 = bias[c0 + 2], b3 = bias[c0 + 3];
    #pragma unroll
    for (int r = 0; r < 8; r++) {
        const float inv = 1.0f / zfin[r0 + r];
        float x0, x1, x2, x3;
        upk2(accA[r], x0, x1);
        upk2(accB[r], x2, x3);
        x0 = x0 * inv + b0;
        x1 = x1 * inv + b1;
        x2 = x2 * inv + b2;
        x3 = x3 * inv + b3;
        x0 = (x0 > 0.f) ? x0 : expm1f(x0);
        x1 = (x1 > 0.f) ? x1 : expm1f(x1);
        x2 = (x2 > 0.f) ? x2 : expm1f(x2);
        x3 = (x3 > 0.f) ? x3 : expm1f(x3);
        *(float4*)&out[((size_t)bn + i0 + r0 + r) * FF + c0] =
            make_float4(x0, x1, x2, x3);
    }
}

// ============================== launch ==============================
extern "C" void kernel_launch(void* const* d_in, const int* in_sizes, int n_in,
                              void* d_out, int out_size) {
    const float* h    = (const float*)d_in[0];  // [8,2048,128]
    const float* adj  = (const float*)d_in[1];  // [2048,2048]
    const float* W    = (const float*)d_in[2];  // [128,128]
    const float* a    = (const float*)d_in[3];  // [256,1]
    const float* bias = (const float*)d_in[4];  // [128]
    float* out = (float*)d_out;                 // [8,2048,128]

    const int smem1 = 65536 + 32768;                       // 96 KB
    const int smem3 = 32768 + 33280 + (3 * TJ + MI) * 4;   // ~67 KB
    cudaFuncSetAttribute(k1_gemm, cudaFuncAttributeMaxDynamicSharedMemorySize, smem1);
    cudaFuncSetAttribute(k3_main, cudaFuncAttributeMaxDynamicSharedMemorySize, smem3);

    k0_wa<<<1, 128>>>(W, a);
    k1_gemm<<<(BB * NN) / MI, 256, smem1>>>(h, W);
    k2_scores<<<(BB * NN) / 8, 256>>>(h);
    k3_main<<<dim3(ITILES, BB), 256, smem3>>>(adj, bias, out);
}

// round 3
// speedup vs baseline: 1.6768x; 1.6768x over previous
#include <cuda_runtime.h>
#include <math.h>
#include <stdint.h>

// Problem constants
#define BB 8
#define NN 2048
#define FF 128
#define TJ 64            // j-tile per iteration in k3
#define SRD 72           // smem row stride (floats): 72 % 32 == 8 -> conflict-free frag loads

typedef unsigned long long ull;

// -------- device scratch --------
__device__ float g_WhT[BB * FF * NN];  // [b][f][j], tf32-rounded, 8 MB
__device__ float g_wa[2 * FF];
__device__ float g_f1[BB * NN];
__device__ float g_f2[BB * NN];
__device__ float g_E1p[BB * NN];
__device__ float g_E1n[BB * NN];
__device__ float g_E2p[BB * NN];
__device__ float g_E2n[BB * NN];

// ======================= helpers =======================
__device__ __forceinline__ uint32_t f2tf32(float x) {
    uint32_t r;
    asm("cvt.rna.tf32.f32 %0, %1;" : "=r"(r) : "f"(x));
    return r;
}
__device__ __forceinline__ ull pk2(float lo, float hi) {
    ull d;
    asm("mov.b64 %0, {%1, %2};" : "=l"(d) : "r"(__float_as_uint(lo)), "r"(__float_as_uint(hi)));
    return d;
}
__device__ __forceinline__ void upk2(ull v, float& lo, float& hi) {
    unsigned a, b;
    asm("mov.b64 {%0, %1}, %2;" : "=r"(a), "=r"(b) : "l"(v));
    lo = __uint_as_float(a); hi = __uint_as_float(b);
}
__device__ __forceinline__ ull pfma(ull a, ull b, ull c) {
    ull d;
    asm("fma.rn.f32x2 %0, %1, %2, %3;" : "=l"(d) : "l"(a), "l"(b), "l"(c));
    return d;
}
// m16n8k8 tf32 MMA (sm_80+ PTX, valid on base sm_103 target)
__device__ __forceinline__ void mma8(float* c, uint32_t a0, uint32_t a1, uint32_t a2,
                                     uint32_t a3, uint32_t b0, uint32_t b1) {
    asm volatile(
        "mma.sync.aligned.m16n8k8.row.col.f32.tf32.tf32.f32 "
        "{%0,%1,%2,%3}, {%4,%5,%6,%7}, {%8,%9}, {%0,%1,%2,%3};"
        : "+f"(c[0]), "+f"(c[1]), "+f"(c[2]), "+f"(c[3])
        : "r"(a0), "r"(a1), "r"(a2), "r"(a3), "r"(b0), "r"(b1));
}

// ===================== k0: wa = W @ a1, W @ a2 =====================
__global__ void k0_wa(const float* __restrict__ W, const float* __restrict__ a) {
    int f = threadIdx.x;
    float s1 = 0.f, s2 = 0.f;
    #pragma unroll 8
    for (int o = 0; o < FF; o++) {
        float w = W[f * FF + o];
        s1 += w * a[o];
        s2 += w * a[FF + o];
    }
    g_wa[f] = s1;
    g_wa[FF + f] = s2;
}

// ===================== k1: WhT = (h @ W)^T, tf32-rounded =====================
__global__ __launch_bounds__(256, 2) void k1_gemm(const float* __restrict__ h,
                                                  const float* __restrict__ W) {
    extern __shared__ char smem1[];
    float* Ws = (float*)smem1;            // 64KB
    float* hs = (float*)(smem1 + 65536);  // 32KB

    int tid = threadIdx.x;
    const float* hb = h + (size_t)blockIdx.x * 64 * FF;

    #pragma unroll
    for (int i = tid * 4; i < FF * FF; i += 1024)
        *(float4*)&Ws[i] = *(const float4*)&W[i];
    #pragma unroll
    for (int i = tid * 4; i < 64 * FF; i += 1024)
        *(float4*)&hs[i] = *(const float4*)&hb[i];
    __syncthreads();

    int c0 = (tid & 31) * 4;
    int r0 = (tid >> 5) * 8;
    ull accA[8], accB[8];
    #pragma unroll
    for (int r = 0; r < 8; r++) { accA[r] = 0ULL; accB[r] = 0ULL; }

    for (int k = 0; k < FF; k++) {
        float4 w = *(float4*)&Ws[k * FF + c0];
        ull wA = pk2(w.x, w.y), wB = pk2(w.z, w.w);
        #pragma unroll
        for (int r = 0; r < 8; r++) {
            float hv = hs[(r0 + r) * FF + k];
            ull hd = pk2(hv, hv);
            accA[r] = pfma(hd, wA, accA[r]);
            accB[r] = pfma(hd, wB, accB[r]);
        }
    }

    float f0[8], f1v[8], f2v[8], f3[8];
    #pragma unroll
    for (int r = 0; r < 8; r++) {
        float x0, x1, x2, x3;
        upk2(accA[r], x0, x1);
        upk2(accB[r], x2, x3);
        f0[r]  = __uint_as_float(f2tf32(x0));
        f1v[r] = __uint_as_float(f2tf32(x1));
        f2v[r] = __uint_as_float(f2tf32(x2));
        f3[r]  = __uint_as_float(f2tf32(x3));
    }
    int b = blockIdx.x >> 5;
    int n0 = (blockIdx.x & 31) * 64;
    #pragma unroll
    for (int e = 0; e < 4; e++) {
        const float* fe = (e == 0) ? f0 : (e == 1) ? f1v : (e == 2) ? f2v : f3;
        float* dst = g_WhT + ((size_t)b * FF + c0 + e) * NN + n0 + r0;
        *(float4*)dst = make_float4(fe[0], fe[1], fe[2], fe[3]);
        *(float4*)(dst + 4) = make_float4(fe[4], fe[5], fe[6], fe[7]);
    }
}

// ===================== k2: f1,f2 + exp tables =====================
__global__ void k2_scores(const float* __restrict__ h) {
    int row = blockIdx.x * 8 + (threadIdx.x >> 5);
    int lane = threadIdx.x & 31;
    float s1 = 0.f, s2 = 0.f;
    #pragma unroll
    for (int q = 0; q < 4; q++) {
        float hv = h[(size_t)row * FF + lane + 32 * q];
        s1 += hv * g_wa[lane + 32 * q];
        s2 += hv * g_wa[FF + lane + 32 * q];
    }
    #pragma unroll
    for (int o = 16; o; o >>= 1) {
        s1 += __shfl_xor_sync(0xFFFFFFFFu, s1, o);
        s2 += __shfl_xor_sync(0xFFFFFFFFu, s2, o);
    }
    if (lane == 0) {
        g_f1[row] = s1;
        g_f2[row] = s2;
        g_E1p[row] = expf(s1);
        g_E1n[row] = expf(0.2f * s1);
        g_E2p[row] = expf(s2);
        g_E2n[row] = expf(0.2f * s2);
    }
}

// ===================== k3: mma.sync tf32 masked-attention GEMM =====================
// grid = 128 (8 b x 16 i-tiles of 128 rows), 256 threads.
// smem (floats): whts[128*72]@0, u_s[128*72]@9216, f2t[64]@18432, ept@+64, ent@+128,
//                z_s[128]@18624, bias_s[128]@18752; total 18880 floats = 75520 B
#define K3_SMEM 75520

__global__ __launch_bounds__(256, 1) void k3_main(const float* __restrict__ adj,
                                                  const float* __restrict__ bias,
                                                  float* __restrict__ out) {
    extern __shared__ float sm[];
    float* whts   = sm;
    float* u_s    = sm + 9216;
    float* f2t    = sm + 18432;
    float* ept    = f2t + 64;
    float* ent    = f2t + 128;
    float* z_s    = f2t + 192;
    float* bias_s = z_s + 128;

    const int tid = threadIdx.x;
    const int b = blockIdx.x >> 4;
    const int i0 = (blockIdx.x & 15) * 128;
    const int bn = b * NN;

    if (tid < 128) bias_s[tid] = bias[tid];

    // ---- builder identity: one row, half of the 64-j tile ----
    const int brow = tid >> 1;
    const int bh = tid & 1;
    const float rf1 = g_f1[bn + i0 + brow];
    const float rEp = g_E1p[bn + i0 + brow];
    const float rEn = g_E1n[bn + i0 + brow];
    const float* adjp = adj + (size_t)(i0 + brow) * NN + bh * 32;
    // ---- WhT stager identity: one feature col, half of j tile ----
    const float* whp = g_WhT + ((size_t)b * FF + brow) * NN + bh * 32;

    // ---- mma identity: 8 warps as 2(M) x 4(N); warp tile 64 x 32 ----
    const int lane = tid & 31, wid = tid >> 5;
    const int mg = wid >> 2, ng = wid & 3;
    const int l4 = lane >> 2, lm = lane & 3;

    float acc[4][4][4] = {};
    float zpart = 0.f;

    for (int iter = 0; iter < 32; iter++) {
        const int jb = iter * TJ;
        __syncthreads();  // previous mma phase done reading smem

        // ---- stage per-j score tables ----
        if (tid < 16)       *(float4*)&f2t[tid * 4]        = *(const float4*)&g_f2[bn + jb + tid * 4];
        else if (tid < 32)  *(float4*)&ept[(tid - 16) * 4] = *(const float4*)&g_E2p[bn + jb + (tid - 16) * 4];
        else if (tid < 48)  *(float4*)&ent[(tid - 32) * 4] = *(const float4*)&g_E2n[bn + jb + (tid - 32) * 4];

        // ---- stage WhT tile, pair-interleaved j layout [j0,j4,j1,j5,j2,j6,j3,j7] ----
        {
            const float* src = whp + jb;
            float* drow = whts + brow * SRD + bh * 32;
            #pragma unroll
            for (int g = 0; g < 4; g++) {
                float4 vA = *(const float4*)(src + g * 8);
                float4 vB = *(const float4*)(src + g * 8 + 4);
                *(float4*)(drow + g * 8)     = make_float4(vA.x, vB.x, vA.y, vB.y);
                *(float4*)(drow + g * 8 + 4) = make_float4(vA.z, vB.z, vA.w, vB.w);
            }
        }
        __syncthreads();

        // ---- build masked-exp U tile (tf32), accumulate Z ----
        {
            const float* ap = adjp + jb;
            const float4* f2q = (const float4*)(f2t + bh * 32);
            const float4* epq = (const float4*)(ept + bh * 32);
            const float4* enq = (const float4*)(ent + bh * 32);
            float* drow = u_s + brow * SRD + bh * 32;
            #pragma unroll
            for (int g = 0; g < 4; g++) {
                float4 aA = *(const float4*)(ap + g * 8);
                float4 aB = *(const float4*)(ap + g * 8 + 4);
                float4 fA = f2q[g * 2], fB = f2q[g * 2 + 1];
                float4 pA = epq[g * 2], pB = epq[g * 2 + 1];
                float4 nA = enq[g * 2], nB = enq[g * 2 + 1];
                float u[8];
                #pragma unroll
                for (int e = 0; e < 4; e++) {
                    float s0 = rf1 + (&fA.x)[e];
                    float v0 = (s0 > 0.f) ? (rEp * (&pA.x)[e]) : (rEn * (&nA.x)[e]);
                    v0 = ((&aA.x)[e] > 0.f) ? v0 : 0.f;
                    u[e] = __uint_as_float(f2tf32(v0));
                    float s1 = rf1 + (&fB.x)[e];
                    float v1 = (s1 > 0.f) ? (rEp * (&pB.x)[e]) : (rEn * (&nB.x)[e]);
                    v1 = ((&aB.x)[e] > 0.f) ? v1 : 0.f;
                    u[e + 4] = __uint_as_float(f2tf32(v1));
                }
                #pragma unroll
                for (int e = 0; e < 8; e++) zpart += u[e];
                *(float4*)(drow + g * 8)     = make_float4(u[0], u[4], u[1], u[5]);
                *(float4*)(drow + g * 8 + 4) = make_float4(u[2], u[6], u[3], u[7]);
            }
        }
        __syncthreads();

        // ---- 8 k-steps of m16n8k8 tf32 mma ----
        #pragma unroll
        for (int ks = 0; ks < 8; ks++) {
            const int kc = ks * 8 + 2 * lm;  // physical pair offset
            uint32_t bf[4][2];
            #pragma unroll
            for (int ni = 0; ni < 4; ni++) {
                int col = ng * 32 + ni * 8 + l4;
                float2 bv = *(const float2*)&whts[col * SRD + kc];
                bf[ni][0] = __float_as_uint(bv.x);
                bf[ni][1] = __float_as_uint(bv.y);
            }
            #pragma unroll
            for (int mi = 0; mi < 4; mi++) {
                int row = mg * 64 + mi * 16 + l4;
                float2 alo = *(const float2*)&u_s[row * SRD + kc];
                float2 ahi = *(const float2*)&u_s[(row + 8) * SRD + kc];
                uint32_t a0 = __float_as_uint(alo.x), a1 = __float_as_uint(ahi.x);
                uint32_t a2 = __float_as_uint(alo.y), a3 = __float_as_uint(ahi.y);
                #pragma unroll
                for (int ni = 0; ni < 4; ni++)
                    mma8(acc[mi][ni], a0, a1, a2, a3, bf[ni][0], bf[ni][1]);
            }
        }
    }

    // ---- Z finalize: halves live in lanes (t, t^1) of same warp ----
    float zo = __shfl_xor_sync(0xFFFFFFFFu, zpart, 1);
    float zt = zpart + zo;
    if (bh == 0) z_s[brow] = zt;
    __syncthreads();

    // ---- epilogue: 1/Z, +bias, ELU, store from fragments ----
    #pragma unroll
    for (int mi = 0; mi < 4; mi++) {
        const int r0 = mg * 64 + mi * 16 + l4;
        const float iz0 = 1.0f / z_s[r0];
        const float iz1 = 1.0f / z_s[r0 + 8];
        float* o0 = out + ((size_t)(bn + i0 + r0)) * FF;
        float* o1 = o0 + (size_t)8 * FF;
        #pragma unroll
        for (int ni = 0; ni < 4; ni++) {
            const int col = ng * 32 + ni * 8 + 2 * lm;
            const float b0 = bias_s[col], b1 = bias_s[col + 1];
            float x0 = acc[mi][ni][0] * iz0 + b0;
            float x1 = acc[mi][ni][1] * iz0 + b1;
            float x2 = acc[mi][ni][2] * iz1 + b0;
            float x3 = acc[mi][ni][3] * iz1 + b1;
            x0 = (x0 > 0.f) ? x0 : expm1f(x0);
            x1 = (x1 > 0.f) ? x1 : expm1f(x1);
            x2 = (x2 > 0.f) ? x2 : expm1f(x2);
            x3 = (x3 > 0.f) ? x3 : expm1f(x3);
            *(float2*)&o0[col] = make_float2(x0, x1);
            *(float2*)&o1[col] = make_float2(x2, x3);
        }
    }
}

// ============================== launch ==============================
extern "C" void kernel_launch(void* const* d_in, const int* in_sizes, int n_in,
                              void* d_out, int out_size) {
    const float* h    = (const float*)d_in[0];
    const float* adj  = (const float*)d_in[1];
    const float* W    = (const float*)d_in[2];
    const float* a    = (const float*)d_in[3];
    const float* bias = (const float*)d_in[4];
    float* out = (float*)d_out;

    const int smem1 = 65536 + 32768;
    cudaFuncSetAttribute(k1_gemm, cudaFuncAttributeMaxDynamicSharedMemorySize, smem1);
    cudaFuncSetAttribute(k3_main, cudaFuncAttributeMaxDynamicSharedMemorySize, K3_SMEM);

    k0_wa<<<1, 128>>>(W, a);
    k1_gemm<<<(BB * NN) / 64, 256, smem1>>>(h, W);
    k2_scores<<<(BB * NN) / 8, 256>>>(h);
    k3_main<<<128, 256, K3_SMEM>>>(adj, bias, out);
}

// round 5
// speedup vs baseline: 1.8576x; 1.1078x over previous
#include <cuda_runtime.h>
#include <math.h>
#include <stdint.h>

// Problem constants
#define BB 8
#define NN 2048
#define FF 128
#define TJ 64            // j-tile per iteration in k3
#define SRD 72           // smem row stride (floats): conflict-free frag loads

typedef unsigned long long ull;

// -------- device scratch --------
__device__ float g_WhT[BB * FF * NN];  // [b][f][j], tf32, pair-interleaved j
__device__ float g_wa[2 * FF];
__device__ float g_f1[BB * NN];
__device__ float g_f2[BB * NN];
__device__ float g_E1p[BB * NN];
__device__ float g_E1n[BB * NN];
__device__ float g_E2p[BB * NN];
__device__ float g_E2n[BB * NN];

// ======================= helpers =======================
__device__ __forceinline__ uint32_t f2tf32(float x) {
    uint32_t r;
    asm("cvt.rna.tf32.f32 %0, %1;" : "=r"(r) : "f"(x));
    return r;
}
__device__ __forceinline__ ull pk2(float lo, float hi) {
    ull d;
    asm("mov.b64 %0, {%1, %2};" : "=l"(d) : "r"(__float_as_uint(lo)), "r"(__float_as_uint(hi)));
    return d;
}
__device__ __forceinline__ void upk2(ull v, float& lo, float& hi) {
    unsigned a, b;
    asm("mov.b64 {%0, %1}, %2;" : "=r"(a), "=r"(b) : "l"(v));
    lo = __uint_as_float(a); hi = __uint_as_float(b);
}
__device__ __forceinline__ ull pfma(ull a, ull b, ull c) {
    ull d;
    asm("fma.rn.f32x2 %0, %1, %2, %3;" : "=l"(d) : "l"(a), "l"(b), "l"(c));
    return d;
}
__device__ __forceinline__ void mma8(float* c, uint32_t a0, uint32_t a1, uint32_t a2,
                                     uint32_t a3, uint32_t b0, uint32_t b1) {
    asm volatile(
        "mma.sync.aligned.m16n8k8.row.col.f32.tf32.tf32.f32 "
        "{%0,%1,%2,%3}, {%4,%5,%6,%7}, {%8,%9}, {%0,%1,%2,%3};"
        : "+f"(c[0]), "+f"(c[1]), "+f"(c[2]), "+f"(c[3])
        : "r"(a0), "r"(a1), "r"(a2), "r"(a3), "r"(b0), "r"(b1));
}
__device__ __forceinline__ uint32_t smem_u32(const void* p) {
    uint32_t a;
    asm("{ .reg .u64 t; cvta.to.shared.u64 t, %1; cvt.u32.u64 %0, t; }" : "=r"(a) : "l"(p));
    return a;
}
__device__ __forceinline__ void cp_async16(uint32_t dst, const float* src) {
    asm volatile("cp.async.cg.shared.global [%0], [%1], 16;" :: "r"(dst), "l"(src));
}

// ===================== k0: wa = W @ a1, W @ a2 =====================
__global__ void k0_wa(const float* __restrict__ W, const float* __restrict__ a) {
    int f = threadIdx.x;
    float s1 = 0.f, s2 = 0.f;
    #pragma unroll 8
    for (int o = 0; o < FF; o++) {
        float w = W[f * FF + o];
        s1 += w * a[o];
        s2 += w * a[FF + o];
    }
    g_wa[f] = s1;
    g_wa[FF + f] = s2;
}

// ===================== k1: WhT = (h @ W)^T, tf32, pair-interleaved j =========
__global__ __launch_bounds__(256, 2) void k1_gemm(const float* __restrict__ h,
                                                  const float* __restrict__ W) {
    extern __shared__ char smem1[];
    float* Ws = (float*)smem1;            // 64KB
    float* hs = (float*)(smem1 + 65536);  // 32KB

    int tid = threadIdx.x;
    const float* hb = h + (size_t)blockIdx.x * 64 * FF;

    #pragma unroll
    for (int i = tid * 4; i < FF * FF; i += 1024)
        *(float4*)&Ws[i] = *(const float4*)&W[i];
    #pragma unroll
    for (int i = tid * 4; i < 64 * FF; i += 1024)
        *(float4*)&hs[i] = *(const float4*)&hb[i];
    __syncthreads();

    int c0 = (tid & 31) * 4;
    int r0 = (tid >> 5) * 8;
    ull accA[8], accB[8];
    #pragma unroll
    for (int r = 0; r < 8; r++) { accA[r] = 0ULL; accB[r] = 0ULL; }

    for (int k = 0; k < FF; k++) {
        float4 w = *(float4*)&Ws[k * FF + c0];
        ull wA = pk2(w.x, w.y), wB = pk2(w.z, w.w);
        #pragma unroll
        for (int r = 0; r < 8; r++) {
            float hv = hs[(r0 + r) * FF + k];
            ull hd = pk2(hv, hv);
            accA[r] = pfma(hd, wA, accA[r]);
            accB[r] = pfma(hd, wB, accB[r]);
        }
    }

    float f0[8], f1v[8], f2v[8], f3[8];
    #pragma unroll
    for (int r = 0; r < 8; r++) {
        float x0, x1, x2, x3;
        upk2(accA[r], x0, x1);
        upk2(accB[r], x2, x3);
        f0[r]  = __uint_as_float(f2tf32(x0));
        f1v[r] = __uint_as_float(f2tf32(x1));
        f2v[r] = __uint_as_float(f2tf32(x2));
        f3[r]  = __uint_as_float(f2tf32(x3));
    }
    int b = blockIdx.x >> 5;
    int n0 = (blockIdx.x & 31) * 64;
    // pair-interleaved j within each 8-group: [j0,j4,j1,j5,j2,j6,j3,j7]
    #pragma unroll
    for (int e = 0; e < 4; e++) {
        const float* fe = (e == 0) ? f0 : (e == 1) ? f1v : (e == 2) ? f2v : f3;
        float* dst = g_WhT + ((size_t)b * FF + c0 + e) * NN + n0 + r0;
        *(float4*)dst = make_float4(fe[0], fe[4], fe[1], fe[5]);
        *(float4*)(dst + 4) = make_float4(fe[2], fe[6], fe[3], fe[7]);
    }
}

// ===================== k2: f1,f2 + exp tables =====================
__global__ void k2_scores(const float* __restrict__ h) {
    int row = blockIdx.x * 8 + (threadIdx.x >> 5);
    int lane = threadIdx.x & 31;
    float s1 = 0.f, s2 = 0.f;
    #pragma unroll
    for (int q = 0; q < 4; q++) {
        float hv = h[(size_t)row * FF + lane + 32 * q];
        s1 += hv * g_wa[lane + 32 * q];
        s2 += hv * g_wa[FF + lane + 32 * q];
    }
    #pragma unroll
    for (int o = 16; o; o >>= 1) {
        s1 += __shfl_xor_sync(0xFFFFFFFFu, s1, o);
        s2 += __shfl_xor_sync(0xFFFFFFFFu, s2, o);
    }
    if (lane == 0) {
        g_f1[row] = s1;
        g_f2[row] = s2;
        g_E1p[row] = expf(s1);
        g_E1n[row] = expf(0.2f * s1);
        g_E2p[row] = expf(s2);
        g_E2n[row] = expf(0.2f * s2);
    }
}

// ===================== k3: pipelined mma.sync tf32 masked-attention GEMM =====
// smem (floats): whts0@0, whts1@9216, u0@18432, u1@27648,
//                ftab@36864, eptab@38912, entab@40960, z@43008, bias@43136
#define K3_SMEM (43264 * 4)

// build masked-exp U for one (row, 32-col half) from prefetched adj regs
__device__ __forceinline__ float build_u(const float4* av, const float* ftab,
                                         const float* eptab, const float* entab,
                                         int joff, float rf1, float rEp, float rEn,
                                         float* drow) {
    float zz = 0.f;
    #pragma unroll
    for (int g = 0; g < 4; g++) {
        float4 fA = *(const float4*)&ftab[joff + g * 8];
        float4 fB = *(const float4*)&ftab[joff + g * 8 + 4];
        float4 pA = *(const float4*)&eptab[joff + g * 8];
        float4 pB = *(const float4*)&eptab[joff + g * 8 + 4];
        float4 nA = *(const float4*)&entab[joff + g * 8];
        float4 nB = *(const float4*)&entab[joff + g * 8 + 4];
        float4 aA = av[2 * g], aB = av[2 * g + 1];
        float u[8];
        #pragma unroll
        for (int e = 0; e < 4; e++) {
            float s0 = rf1 + (&fA.x)[e];
            float v0 = (s0 > 0.f) ? (rEp * (&pA.x)[e]) : (rEn * (&nA.x)[e]);
            v0 = ((&aA.x)[e] > 0.f) ? v0 : 0.f;
            u[e] = __uint_as_float(f2tf32(v0));
            float s1 = rf1 + (&fB.x)[e];
            float v1 = (s1 > 0.f) ? (rEp * (&pB.x)[e]) : (rEn * (&nB.x)[e]);
            v1 = ((&aB.x)[e] > 0.f) ? v1 : 0.f;
            u[e + 4] = __uint_as_float(f2tf32(v1));
        }
        #pragma unroll
        for (int e = 0; e < 8; e++) zz += u[e];
        *(float4*)(drow + g * 8)     = make_float4(u[0], u[4], u[1], u[5]);
        *(float4*)(drow + g * 8 + 4) = make_float4(u[2], u[6], u[3], u[7]);
    }
    return zz;
}

__global__ __launch_bounds__(256) void k3_main(const float* __restrict__ adj,
                                               const float* __restrict__ bias,
                                               float* __restrict__ out) {
    extern __shared__ float sm[];
    float* whts[2] = { sm, sm + 9216 };
    float* u_s[2]  = { sm + 18432, sm + 27648 };
    float* ftab    = sm + 36864;
    float* eptab   = sm + 38912;
    float* entab   = sm + 40960;
    float* z_s     = sm + 43008;
    float* bias_s  = sm + 43136;

    const int tid = threadIdx.x;
    const int b = blockIdx.x >> 4;
    const int i0 = (blockIdx.x & 15) * 128;
    const int bn = b * NN;

    // ---- per-CTA tables (whole 2048-j range, loaded once) ----
    #pragma unroll
    for (int i = tid * 4; i < NN; i += 1024) {
        *(float4*)&ftab[i]  = *(const float4*)&g_f2[bn + i];
        *(float4*)&eptab[i] = *(const float4*)&g_E2p[bn + i];
        *(float4*)&entab[i] = *(const float4*)&g_E2n[bn + i];
    }
    if (tid < 128) bias_s[tid] = bias[tid];

    // ---- builder identity: one row, half of the 64-j tile ----
    const int brow = tid >> 1;
    const int bh = tid & 1;
    const float rf1 = g_f1[bn + i0 + brow];
    const float rEp = g_E1p[bn + i0 + brow];
    const float rEn = g_E1n[bn + i0 + brow];
    const float* adjp = adj + (size_t)(i0 + brow) * NN + bh * 32;
    const float* whp  = g_WhT + ((size_t)b * FF + brow) * NN + bh * 32;
    const int doff = brow * SRD + bh * 32;
    const uint32_t wdst[2] = { smem_u32(whts[0]) + doff * 4, smem_u32(whts[1]) + doff * 4 };

    // ---- mma identity: 8 warps as 2(M) x 4(N); warp tile 64 x 32 ----
    const int lane = tid & 31, wid = tid >> 5;
    const int mg = wid >> 2, ng = wid & 3;
    const int l4 = lane >> 2, lm = lane & 3;

    float acc[4][4][4] = {};
    float zpart = 0.f;
    float4 av[8];

    // ---- tables must be fully staged before any build_u reads them ----
    __syncthreads();

    // ---- prologue: stage tile 0 ----
    #pragma unroll
    for (int c = 0; c < 8; c++) cp_async16(wdst[0] + c * 16, whp + c * 4);
    asm volatile("cp.async.commit_group;");
    #pragma unroll
    for (int k = 0; k < 8; k++) av[k] = ((const float4*)adjp)[k];
    zpart += build_u(av, ftab, eptab, entab, bh * 32, rf1, rEp, rEn, u_s[0] + doff);
    asm volatile("cp.async.wait_group 0;" ::: "memory");
    __syncthreads();

    for (int t = 0; t < 32; t++) {
        const int cur = t & 1, nxt = cur ^ 1;
        const int jb2 = (t + 1) * TJ;

        // ---- issue next tile's loads (async) ----
        if (t < 31) {
            const float* wsrc = whp + jb2;
            #pragma unroll
            for (int c = 0; c < 8; c++) cp_async16(wdst[nxt] + c * 16, wsrc + c * 4);
            asm volatile("cp.async.commit_group;");
            #pragma unroll
            for (int k = 0; k < 8; k++) av[k] = ((const float4*)(adjp + jb2))[k];
        }

        // ---- mma(t): 8 k-steps, latency of the loads above hides here ----
        const float* wb = whts[cur];
        const float* ub = u_s[cur];
        #pragma unroll
        for (int ks = 0; ks < 8; ks++) {
            const int kc = ks * 8 + 2 * lm;
            uint32_t bf[4][2];
            #pragma unroll
            for (int ni = 0; ni < 4; ni++) {
                int col = ng * 32 + ni * 8 + l4;
                float2 bv = *(const float2*)&wb[col * SRD + kc];
                bf[ni][0] = __float_as_uint(bv.x);
                bf[ni][1] = __float_as_uint(bv.y);
            }
            #pragma unroll
            for (int mi = 0; mi < 4; mi++) {
                int row = mg * 64 + mi * 16 + l4;
                float2 alo = *(const float2*)&ub[row * SRD + kc];
                float2 ahi = *(const float2*)&ub[(row + 8) * SRD + kc];
                uint32_t a0 = __float_as_uint(alo.x), a1 = __float_as_uint(ahi.x);
                uint32_t a2 = __float_as_uint(alo.y), a3 = __float_as_uint(ahi.y);
                #pragma unroll
                for (int ni = 0; ni < 4; ni++)
                    mma8(acc[mi][ni], a0, a1, a2, a3, bf[ni][0], bf[ni][1]);
            }
        }

        // ---- convert + store U(t+1) ----
        if (t < 31)
            zpart += build_u(av, ftab, eptab, entab, jb2 + bh * 32,
                             rf1, rEp, rEn, u_s[nxt] + doff);

        asm volatile("cp.async.wait_group 0;" ::: "memory");
        __syncthreads();
    }

    // ---- Z finalize: halves live in lanes (t, t^1) of same warp ----
    float zo = __shfl_xor_sync(0xFFFFFFFFu, zpart, 1);
    float zt = zpart + zo;
    if (bh == 0) z_s[brow] = zt;
    __syncthreads();

    // ---- epilogue: 1/Z, +bias, ELU, store from fragments ----
    #pragma unroll
    for (int mi = 0; mi < 4; mi++) {
        const int r0 = mg * 64 + mi * 16 + l4;
        const float iz0 = 1.0f / z_s[r0];
        const float iz1 = 1.0f / z_s[r0 + 8];
        float* o0 = out + ((size_t)(bn + i0 + r0)) * FF;
        float* o1 = o0 + (size_t)8 * FF;
        #pragma unroll
        for (int ni = 0; ni < 4; ni++) {
            const int col = ng * 32 + ni * 8 + 2 * lm;
            const float b0 = bias_s[col], b1 = bias_s[col + 1];
            float x0 = acc[mi][ni][0] * iz0 + b0;
            float x1 = acc[mi][ni][1] * iz0 + b1;
            float x2 = acc[mi][ni][2] * iz1 + b0;
            float x3 = acc[mi][ni][3] * iz1 + b1;
            x0 = (x0 > 0.f) ? x0 : expm1f(x0);
            x1 = (x1 > 0.f) ? x1 : expm1f(x1);
            x2 = (x2 > 0.f) ? x2 : expm1f(x2);
            x3 = (x3 > 0.f) ? x3 : expm1f(x3);
            *(float2*)&o0[col] = make_float2(x0, x1);
            *(float2*)&o1[col] = make_float2(x2, x3);
        }
    }
}

// ============================== launch ==============================
extern "C" void kernel_launch(void* const* d_in, const int* in_sizes, int n_in,
                              void* d_out, int out_size) {
    const float* h    = (const float*)d_in[0];
    const float* adj  = (const float*)d_in[1];
    const float* W    = (const float*)d_in[2];
    const float* a    = (const float*)d_in[3];
    const float* bias = (const float*)d_in[4];
    float* out = (float*)d_out;

    const int smem1 = 65536 + 32768;
    cudaFuncSetAttribute(k1_gemm, cudaFuncAttributeMaxDynamicSharedMemorySize, smem1);
    cudaFuncSetAttribute(k3_main, cudaFuncAttributeMaxDynamicSharedMemorySize, K3_SMEM);

    k0_wa<<<1, 128>>>(W, a);
    k1_gemm<<<(BB * NN) / 64, 256, smem1>>>(h, W);
    k2_scores<<<(BB * NN) / 8, 256>>>(h);
    k3_main<<<128, 256, K3_SMEM>>>(adj, bias, out);
}

// round 6
// speedup vs baseline: 2.0376x; 1.0969x over previous
#include <cuda_runtime.h>
#include <math.h>
#include <stdint.h>

// Problem constants
#define BB 8
#define NN 2048
#define FF 128
#define TJ 64            // j-tile per iteration in k3
#define SRD 72           // smem row stride (floats): conflict-free frag loads

typedef unsigned long long ull;

// -------- device scratch --------
__device__ float g_WhT[BB * FF * NN];  // [b][f][j], tf32, pair-interleaved j
__device__ float g_wa[2 * FF];
__device__ float g_f1[BB * NN];
__device__ float g_f2[BB * NN];
__device__ float g_E1p[BB * NN];
__device__ float g_E1n[BB * NN];
__device__ float g_E2p[BB * NN];
__device__ float g_E2n[BB * NN];

// ======================= helpers =======================
__device__ __forceinline__ uint32_t f2tf32(float x) {
    uint32_t r;
    asm("cvt.rna.tf32.f32 %0, %1;" : "=r"(r) : "f"(x));
    return r;
}
__device__ __forceinline__ ull pk2(float lo, float hi) {
    ull d;
    asm("mov.b64 %0, {%1, %2};" : "=l"(d) : "r"(__float_as_uint(lo)), "r"(__float_as_uint(hi)));
    return d;
}
__device__ __forceinline__ void upk2(ull v, float& lo, float& hi) {
    unsigned a, b;
    asm("mov.b64 {%0, %1}, %2;" : "=r"(a), "=r"(b) : "l"(v));
    lo = __uint_as_float(a); hi = __uint_as_float(b);
}
__device__ __forceinline__ ull pfma(ull a, ull b, ull c) {
    ull d;
    asm("fma.rn.f32x2 %0, %1, %2, %3;" : "=l"(d) : "l"(a), "l"(b), "l"(c));
    return d;
}
__device__ __forceinline__ void mma8(float* c, uint32_t a0, uint32_t a1, uint32_t a2,
                                     uint32_t a3, uint32_t b0, uint32_t b1) {
    asm volatile(
        "mma.sync.aligned.m16n8k8.row.col.f32.tf32.tf32.f32 "
        "{%0,%1,%2,%3}, {%4,%5,%6,%7}, {%8,%9}, {%0,%1,%2,%3};"
        : "+f"(c[0]), "+f"(c[1]), "+f"(c[2]), "+f"(c[3])
        : "r"(a0), "r"(a1), "r"(a2), "r"(a3), "r"(b0), "r"(b1));
}
__device__ __forceinline__ uint32_t smem_u32(const void* p) {
    uint32_t a;
    asm("{ .reg .u64 t; cvta.to.shared.u64 t, %1; cvt.u32.u64 %0, t; }" : "=r"(a) : "l"(p));
    return a;
}
__device__ __forceinline__ void cp_async16(uint32_t dst, const float* src) {
    asm volatile("cp.async.cg.shared.global [%0], [%1], 16;" :: "r"(dst), "l"(src));
}

// ===================== k0: wa = W @ a1, W @ a2 =====================
__global__ void k0_wa(const float* __restrict__ W, const float* __restrict__ a) {
    int f = threadIdx.x;
    float s1 = 0.f, s2 = 0.f;
    #pragma unroll 8
    for (int o = 0; o < FF; o++) {
        float w = W[f * FF + o];
        s1 += w * a[o];
        s2 += w * a[FF + o];
    }
    g_wa[f] = s1;
    g_wa[FF + f] = s2;
}

// ===================== k1: WhT = (h @ W)^T, tf32, pair-interleaved j =========
__global__ __launch_bounds__(256, 2) void k1_gemm(const float* __restrict__ h,
                                                  const float* __restrict__ W) {
    extern __shared__ char smem1[];
    float* Ws = (float*)smem1;            // 64KB
    float* hs = (float*)(smem1 + 65536);  // 32KB

    int tid = threadIdx.x;
    const float* hb = h + (size_t)blockIdx.x * 64 * FF;

    #pragma unroll
    for (int i = tid * 4; i < FF * FF; i += 1024)
        *(float4*)&Ws[i] = *(const float4*)&W[i];
    #pragma unroll
    for (int i = tid * 4; i < 64 * FF; i += 1024)
        *(float4*)&hs[i] = *(const float4*)&hb[i];
    __syncthreads();

    int c0 = (tid & 31) * 4;
    int r0 = (tid >> 5) * 8;
    ull accA[8], accB[8];
    #pragma unroll
    for (int r = 0; r < 8; r++) { accA[r] = 0ULL; accB[r] = 0ULL; }

    for (int k = 0; k < FF; k++) {
        float4 w = *(float4*)&Ws[k * FF + c0];
        ull wA = pk2(w.x, w.y), wB = pk2(w.z, w.w);
        #pragma unroll
        for (int r = 0; r < 8; r++) {
            float hv = hs[(r0 + r) * FF + k];
            ull hd = pk2(hv, hv);
            accA[r] = pfma(hd, wA, accA[r]);
            accB[r] = pfma(hd, wB, accB[r]);
        }
    }

    float f0[8], f1v[8], f2v[8], f3[8];
    #pragma unroll
    for (int r = 0; r < 8; r++) {
        float x0, x1, x2, x3;
        upk2(accA[r], x0, x1);
        upk2(accB[r], x2, x3);
        f0[r]  = __uint_as_float(f2tf32(x0));
        f1v[r] = __uint_as_float(f2tf32(x1));
        f2v[r] = __uint_as_float(f2tf32(x2));
        f3[r]  = __uint_as_float(f2tf32(x3));
    }
    int b = blockIdx.x >> 5;
    int n0 = (blockIdx.x & 31) * 64;
    // pair-interleaved j within each 8-group: [j0,j4,j1,j5,j2,j6,j3,j7]
    #pragma unroll
    for (int e = 0; e < 4; e++) {
        const float* fe = (e == 0) ? f0 : (e == 1) ? f1v : (e == 2) ? f2v : f3;
        float* dst = g_WhT + ((size_t)b * FF + c0 + e) * NN + n0 + r0;
        *(float4*)dst = make_float4(fe[0], fe[4], fe[1], fe[5]);
        *(float4*)(dst + 4) = make_float4(fe[2], fe[6], fe[3], fe[7]);
    }
}

// ===================== k2: f1,f2 + exp tables =====================
__global__ void k2_scores(const float* __restrict__ h) {
    int row = blockIdx.x * 8 + (threadIdx.x >> 5);
    int lane = threadIdx.x & 31;
    float s1 = 0.f, s2 = 0.f;
    #pragma unroll
    for (int q = 0; q < 4; q++) {
        float hv = h[(size_t)row * FF + lane + 32 * q];
        s1 += hv * g_wa[lane + 32 * q];
        s2 += hv * g_wa[FF + lane + 32 * q];
    }
    #pragma unroll
    for (int o = 16; o; o >>= 1) {
        s1 += __shfl_xor_sync(0xFFFFFFFFu, s1, o);
        s2 += __shfl_xor_sync(0xFFFFFFFFu, s2, o);
    }
    if (lane == 0) {
        g_f1[row] = s1;
        g_f2[row] = s2;
        g_E1p[row] = expf(s1);
        g_E1n[row] = expf(0.2f * s1);
        g_E2p[row] = expf(s2);
        g_E2n[row] = expf(0.2f * s2);
    }
}

// ===================== k3: pipelined mma.sync tf32 masked-attention GEMM =====
// 512 threads / 16 warps. smem (floats): whts0@0, whts1@9216, u0@18432, u1@27648,
//                ftab@36864, eptab@38912, entab@40960, z@43008, bias@43136
#define K3_SMEM (43264 * 4)

// build masked-exp U for one (row, 16-col quarter) from prefetched adj regs
__device__ __forceinline__ float build_u(const float4* av, const float* ftab,
                                         const float* eptab, const float* entab,
                                         int joff, float rf1, float rEp, float rEn,
                                         float* drow) {
    float zz = 0.f;
    #pragma unroll
    for (int g = 0; g < 2; g++) {
        float4 fA = *(const float4*)&ftab[joff + g * 8];
        float4 fB = *(const float4*)&ftab[joff + g * 8 + 4];
        float4 pA = *(const float4*)&eptab[joff + g * 8];
        float4 pB = *(const float4*)&eptab[joff + g * 8 + 4];
        float4 nA = *(const float4*)&entab[joff + g * 8];
        float4 nB = *(const float4*)&entab[joff + g * 8 + 4];
        float4 aA = av[2 * g], aB = av[2 * g + 1];
        float u[8];
        #pragma unroll
        for (int e = 0; e < 4; e++) {
            float s0 = rf1 + (&fA.x)[e];
            float v0 = (s0 > 0.f) ? (rEp * (&pA.x)[e]) : (rEn * (&nA.x)[e]);
            v0 = ((&aA.x)[e] > 0.f) ? v0 : 0.f;
            u[e] = __uint_as_float(f2tf32(v0));
            float s1 = rf1 + (&fB.x)[e];
            float v1 = (s1 > 0.f) ? (rEp * (&pB.x)[e]) : (rEn * (&nB.x)[e]);
            v1 = ((&aB.x)[e] > 0.f) ? v1 : 0.f;
            u[e + 4] = __uint_as_float(f2tf32(v1));
        }
        #pragma unroll
        for (int e = 0; e < 8; e++) zz += u[e];
        *(float4*)(drow + g * 8)     = make_float4(u[0], u[4], u[1], u[5]);
        *(float4*)(drow + g * 8 + 4) = make_float4(u[2], u[6], u[3], u[7]);
    }
    return zz;
}

__global__ __launch_bounds__(512, 1) void k3_main(const float* __restrict__ adj,
                                                  const float* __restrict__ bias,
                                                  float* __restrict__ out) {
    extern __shared__ float sm[];
    float* whts[2] = { sm, sm + 9216 };
    float* u_s[2]  = { sm + 18432, sm + 27648 };
    float* ftab    = sm + 36864;
    float* eptab   = sm + 38912;
    float* entab   = sm + 40960;
    float* z_s     = sm + 43008;
    float* bias_s  = sm + 43136;

    const int tid = threadIdx.x;
    const int b = blockIdx.x >> 4;
    const int i0 = (blockIdx.x & 15) * 128;
    const int bn = b * NN;

    // ---- per-CTA tables (whole 2048-j range, loaded once) ----
    {
        int i = tid * 4;  // 512 threads x 4 floats = 2048
        *(float4*)&ftab[i]  = *(const float4*)&g_f2[bn + i];
        *(float4*)&eptab[i] = *(const float4*)&g_E2p[bn + i];
        *(float4*)&entab[i] = *(const float4*)&g_E2n[bn + i];
    }
    if (tid < 128) bias_s[tid] = bias[tid];

    // ---- builder identity: one row, 16-j quarter of the 64-j tile ----
    const int brow = tid >> 2;
    const int bh = tid & 3;
    const float rf1 = g_f1[bn + i0 + brow];
    const float rEp = g_E1p[bn + i0 + brow];
    const float rEn = g_E1n[bn + i0 + brow];
    const float* adjp = adj + (size_t)(i0 + brow) * NN + bh * 16;
    const float* whp  = g_WhT + ((size_t)b * FF + brow) * NN + bh * 16;
    const int doff = brow * SRD + bh * 16;
    const uint32_t wdst[2] = { smem_u32(whts[0]) + doff * 4, smem_u32(whts[1]) + doff * 4 };

    // ---- mma identity: 16 warps as 4(M) x 4(N); warp tile 32 x 32 ----
    const int lane = tid & 31, wid = tid >> 5;
    const int mg = wid >> 2, ng = wid & 3;
    const int l4 = lane >> 2, lm = lane & 3;

    float acc[2][4][4] = {};
    float zpart = 0.f;
    float4 av[4];

    // ---- tables must be fully staged before any build_u reads them ----
    __syncthreads();

    // ---- prologue: stage tile 0 ----
    #pragma unroll
    for (int c = 0; c < 4; c++) cp_async16(wdst[0] + c * 16, whp + c * 4);
    asm volatile("cp.async.commit_group;");
    #pragma unroll
    for (int k = 0; k < 4; k++) av[k] = ((const float4*)adjp)[k];
    zpart += build_u(av, ftab, eptab, entab, bh * 16, rf1, rEp, rEn, u_s[0] + doff);
    asm volatile("cp.async.wait_group 0;" ::: "memory");
    __syncthreads();

    for (int t = 0; t < 32; t++) {
        const int cur = t & 1, nxt = cur ^ 1;
        const int jb2 = (t + 1) * TJ;

        // ---- issue next tile's loads (async) ----
        if (t < 31) {
            const float* wsrc = whp + jb2;
            #pragma unroll
            for (int c = 0; c < 4; c++) cp_async16(wdst[nxt] + c * 16, wsrc + c * 4);
            asm volatile("cp.async.commit_group;");
            #pragma unroll
            for (int k = 0; k < 4; k++) av[k] = ((const float4*)(adjp + jb2))[k];
        }

        // ---- mma(t): 8 k-steps, latency of the loads above hides here ----
        const float* wb = whts[cur];
        const float* ub = u_s[cur];
        #pragma unroll
        for (int ks = 0; ks < 8; ks++) {
            const int kc = ks * 8 + 2 * lm;
            uint32_t bf[4][2];
            #pragma unroll
            for (int ni = 0; ni < 4; ni++) {
                int col = ng * 32 + ni * 8 + l4;
                float2 bv = *(const float2*)&wb[col * SRD + kc];
                bf[ni][0] = __float_as_uint(bv.x);
                bf[ni][1] = __float_as_uint(bv.y);
            }
            #pragma unroll
            for (int mi = 0; mi < 2; mi++) {
                int row = mg * 32 + mi * 16 + l4;
                float2 alo = *(const float2*)&ub[row * SRD + kc];
                float2 ahi = *(const float2*)&ub[(row + 8) * SRD + kc];
                uint32_t a0 = __float_as_uint(alo.x), a1 = __float_as_uint(ahi.x);
                uint32_t a2 = __float_as_uint(alo.y), a3 = __float_as_uint(ahi.y);
                #pragma unroll
                for (int ni = 0; ni < 4; ni++)
                    mma8(acc[mi][ni], a0, a1, a2, a3, bf[ni][0], bf[ni][1]);
            }
        }

        // ---- convert + store U(t+1) ----
        if (t < 31)
            zpart += build_u(av, ftab, eptab, entab, jb2 + bh * 16,
                             rf1, rEp, rEn, u_s[nxt] + doff);

        asm volatile("cp.async.wait_group 0;" ::: "memory");
        __syncthreads();
    }

    // ---- Z finalize: 4 quarter-threads per row are lanes (t^1, t^2) ----
    zpart += __shfl_xor_sync(0xFFFFFFFFu, zpart, 1);
    zpart += __shfl_xor_sync(0xFFFFFFFFu, zpart, 2);
    if (bh == 0) z_s[brow] = zpart;
    __syncthreads();

    // ---- epilogue: 1/Z, +bias, ELU, store from fragments ----
    #pragma unroll
    for (int mi = 0; mi < 2; mi++) {
        const int r0 = mg * 32 + mi * 16 + l4;
        const float iz0 = 1.0f / z_s[r0];
        const float iz1 = 1.0f / z_s[r0 + 8];
        float* o0 = out + ((size_t)(bn + i0 + r0)) * FF;
        float* o1 = o0 + (size_t)8 * FF;
        #pragma unroll
        for (int ni = 0; ni < 4; ni++) {
            const int col = ng * 32 + ni * 8 + 2 * lm;
            const float b0 = bias_s[col], b1 = bias_s[col + 1];
            float x0 = acc[mi][ni][0] * iz0 + b0;
            float x1 = acc[mi][ni][1] * iz0 + b1;
            float x2 = acc[mi][ni][2] * iz1 + b0;
            float x3 = acc[mi][ni][3] * iz1 + b1;
            x0 = (x0 > 0.f) ? x0 : expm1f(x0);
            x1 = (x1 > 0.f) ? x1 : expm1f(x1);
            x2 = (x2 > 0.f) ? x2 : expm1f(x2);
            x3 = (x3 > 0.f) ? x3 : expm1f(x3);
            *(float2*)&o0[col] = make_float2(x0, x1);
            *(float2*)&o1[col] = make_float2(x2, x3);
        }
    }
}

// ============================== launch ==============================
extern "C" void kernel_launch(void* const* d_in, const int* in_sizes, int n_in,
                              void* d_out, int out_size) {
    const float* h    = (const float*)d_in[0];
    const float* adj  = (const float*)d_in[1];
    const float* W    = (const float*)d_in[2];
    const float* a    = (const float*)d_in[3];
    const float* bias = (const float*)d_in[4];
    float* out = (float*)d_out;

    const int smem1 = 65536 + 32768;
    cudaFuncSetAttribute(k1_gemm, cudaFuncAttributeMaxDynamicSharedMemorySize, smem1);
    cudaFuncSetAttribute(k3_main, cudaFuncAttributeMaxDynamicSharedMemorySize, K3_SMEM);

    k0_wa<<<1, 128>>>(W, a);
    k1_gemm<<<(BB * NN) / 64, 256, smem1>>>(h, W);
    k2_scores<<<(BB * NN) / 8, 256>>>(h);
    k3_main<<<128, 512, K3_SMEM>>>(adj, bias, out);
}

// round 7
// speedup vs baseline: 2.0983x; 1.0298x over previous
#include <cuda_runtime.h>
#include <math.h>
#include <stdint.h>

// Problem constants
#define BB 8
#define NN 2048
#define FF 128
#define TJ 64            // j-tile per iteration in k3
#define SRD 80           // smem row stride (floats): SRD/4 % 8 == 4 -> conflict-free LDS.128 frags

typedef unsigned long long ull;

// -------- device scratch --------
__device__ float g_WhT[BB * FF * NN];  // [b][f][j], tf32, 16-group k-pair interleaved j
__device__ float g_wa[2 * FF];
__device__ float g_f1[BB * NN];
__device__ float g_f2[BB * NN];
__device__ float g_E1p[BB * NN];
__device__ float g_E1n[BB * NN];
__device__ float g_E2p[BB * NN];
__device__ float g_E2n[BB * NN];

// ======================= helpers =======================
__device__ __forceinline__ uint32_t f2tf32(float x) {
    uint32_t r;
    asm("cvt.rna.tf32.f32 %0, %1;" : "=r"(r) : "f"(x));
    return r;
}
__device__ __forceinline__ ull pk2(float lo, float hi) {
    ull d;
    asm("mov.b64 %0, {%1, %2};" : "=l"(d) : "r"(__float_as_uint(lo)), "r"(__float_as_uint(hi)));
    return d;
}
__device__ __forceinline__ void upk2(ull v, float& lo, float& hi) {
    unsigned a, b;
    asm("mov.b64 {%0, %1}, %2;" : "=r"(a), "=r"(b) : "l"(v));
    lo = __uint_as_float(a); hi = __uint_as_float(b);
}
__device__ __forceinline__ ull pfma(ull a, ull b, ull c) {
    ull d;
    asm("fma.rn.f32x2 %0, %1, %2, %3;" : "=l"(d) : "l"(a), "l"(b), "l"(c));
    return d;
}
__device__ __forceinline__ void mma8(float* c, uint32_t a0, uint32_t a1, uint32_t a2,
                                     uint32_t a3, uint32_t b0, uint32_t b1) {
    asm volatile(
        "mma.sync.aligned.m16n8k8.row.col.f32.tf32.tf32.f32 "
        "{%0,%1,%2,%3}, {%4,%5,%6,%7}, {%8,%9}, {%0,%1,%2,%3};"
        : "+f"(c[0]), "+f"(c[1]), "+f"(c[2]), "+f"(c[3])
        : "r"(a0), "r"(a1), "r"(a2), "r"(a3), "r"(b0), "r"(b1));
}
__device__ __forceinline__ uint32_t smem_u32(const void* p) {
    uint32_t a;
    asm("{ .reg .u64 t; cvta.to.shared.u64 t, %1; cvt.u32.u64 %0, t; }" : "=r"(a) : "l"(p));
    return a;
}
__device__ __forceinline__ void cp_async16(uint32_t dst, const float* src) {
    asm volatile("cp.async.cg.shared.global [%0], [%1], 16;" :: "r"(dst), "l"(src));
}

// ===================== k0: wa = W @ a1, W @ a2 =====================
__global__ void k0_wa(const float* __restrict__ W, const float* __restrict__ a) {
    int f = threadIdx.x;
    float s1 = 0.f, s2 = 0.f;
    #pragma unroll 8
    for (int o = 0; o < FF; o++) {
        float w = W[f * FF + o];
        s1 += w * a[o];
        s2 += w * a[FF + o];
    }
    g_wa[f] = s1;
    g_wa[FF + f] = s2;
}

// ===================== k1: WhT = (h @ W)^T, tf32, 16-group interleaved j =====
__global__ __launch_bounds__(256, 2) void k1_gemm(const float* __restrict__ h,
                                                  const float* __restrict__ W) {
    extern __shared__ char smem1[];
    float* Ws = (float*)smem1;            // 64KB
    float* hs = (float*)(smem1 + 65536);  // 32KB

    int tid = threadIdx.x;
    const float* hb = h + (size_t)blockIdx.x * 64 * FF;

    #pragma unroll
    for (int i = tid * 4; i < FF * FF; i += 1024)
        *(float4*)&Ws[i] = *(const float4*)&W[i];
    #pragma unroll
    for (int i = tid * 4; i < 64 * FF; i += 1024)
        *(float4*)&hs[i] = *(const float4*)&hb[i];
    __syncthreads();

    int c0 = (tid & 31) * 4;
    int r0 = (tid >> 5) * 8;
    ull accA[8], accB[8];
    #pragma unroll
    for (int r = 0; r < 8; r++) { accA[r] = 0ULL; accB[r] = 0ULL; }

    for (int k = 0; k < FF; k++) {
        float4 w = *(float4*)&Ws[k * FF + c0];
        ull wA = pk2(w.x, w.y), wB = pk2(w.z, w.w);
        #pragma unroll
        for (int r = 0; r < 8; r++) {
            float hv = hs[(r0 + r) * FF + k];
            ull hd = pk2(hv, hv);
            accA[r] = pfma(hd, wA, accA[r]);
            accB[r] = pfma(hd, wB, accB[r]);
        }
    }

    float f0[8], f1v[8], f2v[8], f3[8];
    #pragma unroll
    for (int r = 0; r < 8; r++) {
        float x0, x1, x2, x3;
        upk2(accA[r], x0, x1);
        upk2(accB[r], x2, x3);
        f0[r]  = __uint_as_float(f2tf32(x0));
        f1v[r] = __uint_as_float(f2tf32(x1));
        f2v[r] = __uint_as_float(f2tf32(x2));
        f3[r]  = __uint_as_float(f2tf32(x3));
    }
    int b = blockIdx.x >> 5;
    int n0 = (blockIdx.x & 31) * 64;
    // 16-group interleave: logical L -> physical p = 4*(L&3) + 2*(L>>3) + ((L&7)>>2)
    // this warp's 8 js have constant parity = (r0>>3)&1, L = parity*8 + r
    int parity = (r0 >> 3) & 1;
    int base16 = n0 + (r0 & ~15);
    #pragma unroll
    for (int e = 0; e < 4; e++) {
        const float* fe = (e == 0) ? f0 : (e == 1) ? f1v : (e == 2) ? f2v : f3;
        float* dst = g_WhT + ((size_t)b * FF + c0 + e) * NN + base16 + parity * 2;
        *(float2*)&dst[0]  = make_float2(fe[0], fe[4]);
        *(float2*)&dst[4]  = make_float2(fe[1], fe[5]);
        *(float2*)&dst[8]  = make_float2(fe[2], fe[6]);
        *(float2*)&dst[12] = make_float2(fe[3], fe[7]);
    }
}

// ===================== k2: f1,f2 + exp tables =====================
__global__ void k2_scores(const float* __restrict__ h) {
    int row = blockIdx.x * 8 + (threadIdx.x >> 5);
    int lane = threadIdx.x & 31;
    float s1 = 0.f, s2 = 0.f;
    #pragma unroll
    for (int q = 0; q < 4; q++) {
        float hv = h[(size_t)row * FF + lane + 32 * q];
        s1 += hv * g_wa[lane + 32 * q];
        s2 += hv * g_wa[FF + lane + 32 * q];
    }
    #pragma unroll
    for (int o = 16; o; o >>= 1) {
        s1 += __shfl_xor_sync(0xFFFFFFFFu, s1, o);
        s2 += __shfl_xor_sync(0xFFFFFFFFu, s2, o);
    }
    if (lane == 0) {
        g_f1[row] = s1;
        g_f2[row] = s2;
        g_E1p[row] = expf(s1);
        g_E1n[row] = expf(0.2f * s1);
        g_E2p[row] = expf(s2);
        g_E2n[row] = expf(0.2f * s2);
    }
}

// ===================== k3: pipelined mma.sync tf32 masked-attention GEMM =====
// 512 threads / 16 warps. smem (floats): whts0@0, whts1@10240, u0@20480,
// u1@30720, ftab@40960, eptab@43008, entab@45056, z@47104, bias@47232
#define K3_SMEM (47360 * 4)

// build masked-exp U for one (row, 16-j group); store k-pair interleaved
__device__ __forceinline__ float build_u(const float4* av, const float* ftab,
                                         const float* eptab, const float* entab,
                                         int joff, float rf1, float rEp, float rEn,
                                         float* drow) {
    float u[16];
    float zz = 0.f;
    #pragma unroll
    for (int g = 0; g < 4; g++) {
        float4 f = *(const float4*)&ftab[joff + g * 4];
        float4 p = *(const float4*)&eptab[joff + g * 4];
        float4 n = *(const float4*)&entab[joff + g * 4];
        float4 a = av[g];
        #pragma unroll
        for (int e = 0; e < 4; e++) {
            float s = rf1 + (&f.x)[e];
            float v = (s > 0.f) ? (rEp * (&p.x)[e]) : (rEn * (&n.x)[e]);
            v = ((&a.x)[e] > 0.f) ? v : 0.f;
            u[g * 4 + e] = __uint_as_float(f2tf32(v));
            zz += u[g * 4 + e];
        }
    }
    // permuted store: physical float4 g = (u[g], u[g+4], u[g+8], u[g+12])
    #pragma unroll
    for (int g = 0; g < 4; g++)
        *(float4*)(drow + g * 4) = make_float4(u[g], u[g + 4], u[g + 8], u[g + 12]);
    return zz;
}

__global__ __launch_bounds__(512, 1) void k3_main(const float* __restrict__ adj,
                                                  const float* __restrict__ bias,
                                                  float* __restrict__ out) {
    extern __shared__ float sm[];
    float* whts[2] = { sm, sm + 10240 };
    float* u_s[2]  = { sm + 20480, sm + 30720 };
    float* ftab    = sm + 40960;
    float* eptab   = sm + 43008;
    float* entab   = sm + 45056;
    float* z_s     = sm + 47104;
    float* bias_s  = sm + 47232;

    const int tid = threadIdx.x;
    const int b = blockIdx.x >> 4;
    const int i0 = (blockIdx.x & 15) * 128;
    const int bn = b * NN;

    // ---- per-CTA tables (whole 2048-j range, loaded once) ----
    {
        int i = tid * 4;  // 512 threads x 4 floats = 2048
        *(float4*)&ftab[i]  = *(const float4*)&g_f2[bn + i];
        *(float4*)&eptab[i] = *(const float4*)&g_E2p[bn + i];
        *(float4*)&entab[i] = *(const float4*)&g_E2n[bn + i];
    }
    if (tid < 128) bias_s[tid] = bias[tid];

    // ---- builder identity: one row, one 16-j group of the 64-j tile ----
    const int brow = tid >> 2;
    const int bh = tid & 3;
    const float rf1 = g_f1[bn + i0 + brow];
    const float rEp = g_E1p[bn + i0 + brow];
    const float rEn = g_E1n[bn + i0 + brow];
    const float* adjp = adj + (size_t)(i0 + brow) * NN + bh * 16;
    const float* whp  = g_WhT + ((size_t)b * FF + brow) * NN + bh * 16;
    const int doff = brow * SRD + bh * 16;
    const uint32_t wdst[2] = { smem_u32(whts[0]) + doff * 4, smem_u32(whts[1]) + doff * 4 };

    // ---- mma identity: 16 warps as 4(M) x 4(N); warp tile 32 x 32 ----
    const int lane = tid & 31, wid = tid >> 5;
    const int mg = wid >> 2, ng = wid & 3;
    const int l4 = lane >> 2, lm = lane & 3;

    float acc[2][4][4] = {};
    float zpart = 0.f;
    float4 av[4];

    // ---- tables must be fully staged before any build_u reads them ----
    __syncthreads();

    // ---- prologue: stage tile 0 ----
    #pragma unroll
    for (int c = 0; c < 4; c++) cp_async16(wdst[0] + c * 16, whp + c * 4);
    asm volatile("cp.async.commit_group;");
    #pragma unroll
    for (int k = 0; k < 4; k++) av[k] = ((const float4*)adjp)[k];
    zpart += build_u(av, ftab, eptab, entab, bh * 16, rf1, rEp, rEn, u_s[0] + doff);
    asm volatile("cp.async.wait_group 0;" ::: "memory");
    __syncthreads();

    for (int t = 0; t < 32; t++) {
        const int cur = t & 1, nxt = cur ^ 1;
        const int jb2 = (t + 1) * TJ;

        // ---- issue next tile's loads (async) ----
        if (t < 31) {
            const float* wsrc = whp + jb2;
            #pragma unroll
            for (int c = 0; c < 4; c++) cp_async16(wdst[nxt] + c * 16, wsrc + c * 4);
            asm volatile("cp.async.commit_group;");
            #pragma unroll
            for (int k = 0; k < 4; k++) av[k] = ((const float4*)(adjp + jb2))[k];
        }

        // ---- mma(t): 4 q-steps x 2 k-steps; LDS.128 dual-k fragment loads ----
        const float* wb = whts[cur];
        const float* ub = u_s[cur];
        #pragma unroll
        for (int q = 0; q < 4; q++) {
            const int kc = q * 16 + lm * 4;
            float4 bv[4];
            #pragma unroll
            for (int ni = 0; ni < 4; ni++)
                bv[ni] = *(const float4*)&wb[(ng * 32 + ni * 8 + l4) * SRD + kc];
            float4 al[2], ah[2];
            #pragma unroll
            for (int mi = 0; mi < 2; mi++) {
                int row = mg * 32 + mi * 16 + l4;
                al[mi] = *(const float4*)&ub[row * SRD + kc];
                ah[mi] = *(const float4*)&ub[(row + 8) * SRD + kc];
            }
            // ks = 2q
            #pragma unroll
            for (int mi = 0; mi < 2; mi++) {
                uint32_t a0 = __float_as_uint(al[mi].x), a1 = __float_as_uint(ah[mi].x);
                uint32_t a2 = __float_as_uint(al[mi].y), a3 = __float_as_uint(ah[mi].y);
                #pragma unroll
                for (int ni = 0; ni < 4; ni++)
                    mma8(acc[mi][ni], a0, a1, a2, a3,
                         __float_as_uint(bv[ni].x), __float_as_uint(bv[ni].y));
            }
            // ks = 2q+1
            #pragma unroll
            for (int mi = 0; mi < 2; mi++) {
                uint32_t a0 = __float_as_uint(al[mi].z), a1 = __float_as_uint(ah[mi].z);
                uint32_t a2 = __float_as_uint(al[mi].w), a3 = __float_as_uint(ah[mi].w);
                #pragma unroll
                for (int ni = 0; ni < 4; ni++)
                    mma8(acc[mi][ni], a0, a1, a2, a3,
                         __float_as_uint(bv[ni].z), __float_as_uint(bv[ni].w));
            }
        }

        // ---- convert + store U(t+1) ----
        if (t < 31)
            zpart += build_u(av, ftab, eptab, entab, jb2 + bh * 16,
                             rf1, rEp, rEn, u_s[nxt] + doff);

        asm volatile("cp.async.wait_group 0;" ::: "memory");
        __syncthreads();
    }

    // ---- Z finalize: 4 group-threads per row are adjacent lanes ----
    zpart += __shfl_xor_sync(0xFFFFFFFFu, zpart, 1);
    zpart += __shfl_xor_sync(0xFFFFFFFFu, zpart, 2);
    if (bh == 0) z_s[brow] = zpart;
    __syncthreads();

    // ---- epilogue: 1/Z, +bias, ELU, store from fragments ----
    #pragma unroll
    for (int mi = 0; mi < 2; mi++) {
        const int r0 = mg * 32 + mi * 16 + l4;
        const float iz0 = 1.0f / z_s[r0];
        const float iz1 = 1.0f / z_s[r0 + 8];
        float* o0 = out + ((size_t)(bn + i0 + r0)) * FF;
        float* o1 = o0 + (size_t)8 * FF;
        #pragma unroll
        for (int ni = 0; ni < 4; ni++) {
            const int col = ng * 32 + ni * 8 + 2 * lm;
            const float b0 = bias_s[col], b1 = bias_s[col + 1];
            float x0 = acc[mi][ni][0] * iz0 + b0;
            float x1 = acc[mi][ni][1] * iz0 + b1;
            float x2 = acc[mi][ni][2] * iz1 + b0;
            float x3 = acc[mi][ni][3] * iz1 + b1;
            x0 = (x0 > 0.f) ? x0 : expm1f(x0);
            x1 = (x1 > 0.f) ? x1 : expm1f(x1);
            x2 = (x2 > 0.f) ? x2 : expm1f(x2);
            x3 = (x3 > 0.f) ? x3 : expm1f(x3);
            *(float2*)&o0[col] = make_float2(x0, x1);
            *(float2*)&o1[col] = make_float2(x2, x3);
        }
    }
}

// ============================== launch ==============================
extern "C" void kernel_launch(void* const* d_in, const int* in_sizes, int n_in,
                              void* d_out, int out_size) {
    const float* h    = (const float*)d_in[0];
    const float* adj  = (const float*)d_in[1];
    const float* W    = (const float*)d_in[2];
    const float* a    = (const float*)d_in[3];
    const float* bias = (const float*)d_in[4];
    float* out = (float*)d_out;

    const int smem1 = 65536 + 32768;
    cudaFuncSetAttribute(k1_gemm, cudaFuncAttributeMaxDynamicSharedMemorySize, smem1);
    cudaFuncSetAttribute(k3_main, cudaFuncAttributeMaxDynamicSharedMemorySize, K3_SMEM);

    k0_wa<<<1, 128>>>(W, a);
    k1_gemm<<<(BB * NN) / 64, 256, smem1>>>(h, W);
    k2_scores<<<(BB * NN) / 8, 256>>>(h);
    k3_main<<<128, 512, K3_SMEM>>>(adj, bias, out);
}

// round 9
// speedup vs baseline: 2.3077x; 1.0998x over previous
#include <cuda_runtime.h>
#include <cuda_fp16.h>
#include <math.h>
#include <stdint.h>

// Problem constants
#define BB 8
#define NN 2048
#define FF 128
#define TJ 64            // j-tile per iteration in k3
#define SRD32 36         // smem row stride (uint32): conflict-free LDS.128/STS.128

typedef unsigned long long ull;

// -------- device scratch --------
__device__ uint32_t g_WhT32[BB * FF * NN / 2];  // [b][f][j/2] half2, sigma-permuted, 4MB
__device__ float g_adjP[NN * NN];               // sigma-permuted adjacency, 16MB
__device__ float g_wa[2 * FF];
__device__ float g_f1[BB * NN];
__device__ float g_f2[BB * NN];                 // j-permuted
__device__ float g_E1p[BB * NN];
__device__ float g_E1n[BB * NN];
__device__ float g_E2p[BB * NN];                // j-permuted
__device__ float g_E2n[BB * NN];                // j-permuted

// ======================= helpers =======================
__device__ __forceinline__ ull pk2(float lo, float hi) {
    ull d;
    asm("mov.b64 %0, {%1, %2};" : "=l"(d) : "r"(__float_as_uint(lo)), "r"(__float_as_uint(hi)));
    return d;
}
__device__ __forceinline__ void upk2(ull v, float& lo, float& hi) {
    unsigned a, b;
    asm("mov.b64 {%0, %1}, %2;" : "=r"(a), "=r"(b) : "l"(v));
    lo = __uint_as_float(a); hi = __uint_as_float(b);
}
__device__ __forceinline__ ull pfma(ull a, ull b, ull c) {
    ull d;
    asm("fma.rn.f32x2 %0, %1, %2, %3;" : "=l"(d) : "l"(a), "l"(b), "l"(c));
    return d;
}
// pack two f32 -> half2 (lo -> low half, hi -> high half)
__device__ __forceinline__ uint32_t pkhf(float lo, float hi) {
    __half2 t = __floats2half2_rn(lo, hi);
    return *reinterpret_cast<uint32_t*>(&t);
}
// m16n8k16 f16 MMA, fp32 accumulate (sm_80+ PTX, valid on base sm_103)
__device__ __forceinline__ void mma16(float* c, uint32_t a0, uint32_t a1, uint32_t a2,
                                      uint32_t a3, uint32_t b0, uint32_t b1) {
    asm volatile(
        "mma.sync.aligned.m16n8k16.row.col.f32.f16.f16.f32 "
        "{%0,%1,%2,%3}, {%4,%5,%6,%7}, {%8,%9}, {%0,%1,%2,%3};"
        : "+f"(c[0]), "+f"(c[1]), "+f"(c[2]), "+f"(c[3])
        : "r"(a0), "r"(a1), "r"(a2), "r"(a3), "r"(b0), "r"(b1));
}
__device__ __forceinline__ uint32_t smem_u32(const void* p) {
    uint32_t a;
    asm("{ .reg .u64 t; cvta.to.shared.u64 t, %1; cvt.u32.u64 %0, t; }" : "=r"(a) : "l"(p));
    return a;
}
__device__ __forceinline__ void cp_async16(uint32_t dst, const void* src) {
    asm volatile("cp.async.cg.shared.global [%0], [%1], 16;" :: "r"(dst), "l"(src));
}
// sigma: physical position of logical j within its 32-group
__device__ __forceinline__ int sigma32(int j) {
    return (j & ~31) | (8 * ((j >> 1) & 3) + 2 * ((j >> 3) & 3) + (j & 1));
}

// ===================== k_adjP: permute adjacency into sigma order ============
__global__ void k_adjP(const float* __restrict__ adj) {
    size_t idx = ((size_t)blockIdx.x * 256 + threadIdx.x) * 4;
    float4 v = *(const float4*)&adj[idx];
    int jc = (int)(idx & (NN - 1));
    size_t rowbase = idx & ~(size_t)(NN - 1);
    #pragma unroll
    for (int e = 0; e < 4; e++)
        g_adjP[rowbase + sigma32(jc + e)] = (&v.x)[e];
}

// ===================== k0: wa = W @ a1, W @ a2 =====================
__global__ void k0_wa(const float* __restrict__ W, const float* __restrict__ a) {
    int f = threadIdx.x;
    float s1 = 0.f, s2 = 0.f;
    #pragma unroll 8
    for (int o = 0; o < FF; o++) {
        float w = W[f * FF + o];
        s1 += w * a[o];
        s2 += w * a[FF + o];
    }
    g_wa[f] = s1;
    g_wa[FF + f] = s2;
}

// ===================== k1: WhT = (h @ W)^T, half2, sigma-permuted ============
__global__ __launch_bounds__(256, 2) void k1_gemm(const float* __restrict__ h,
                                                  const float* __restrict__ W) {
    extern __shared__ char smem1[];
    float* Ws = (float*)smem1;            // 64KB
    float* hs = (float*)(smem1 + 65536);  // 32KB

    int tid = threadIdx.x;
    const float* hb = h + (size_t)blockIdx.x * 64 * FF;

    #pragma unroll
    for (int i = tid * 4; i < FF * FF; i += 1024)
        *(float4*)&Ws[i] = *(const float4*)&W[i];
    #pragma unroll
    for (int i = tid * 4; i < 64 * FF; i += 1024)
        *(float4*)&hs[i] = *(const float4*)&hb[i];
    __syncthreads();

    int c0 = (tid & 31) * 4;
    int r0 = (tid >> 5) * 8;      // 8 consecutive j-rows
    ull accA[8], accB[8];
    #pragma unroll
    for (int r = 0; r < 8; r++) { accA[r] = 0ULL; accB[r] = 0ULL; }

    for (int k = 0; k < FF; k++) {
        float4 w = *(float4*)&Ws[k * FF + c0];
        ull wA = pk2(w.x, w.y), wB = pk2(w.z, w.w);
        #pragma unroll
        for (int r = 0; r < 8; r++) {
            float hv = hs[(r0 + r) * FF + k];
            ull hd = pk2(hv, hv);
            accA[r] = pfma(hd, wA, accA[r]);
            accB[r] = pfma(hd, wB, accB[r]);
        }
    }

    float f0[8], f1v[8], f2v[8], f3[8];
    #pragma unroll
    for (int r = 0; r < 8; r++) {
        upk2(accA[r], f0[r], f1v[r]);
        upk2(accB[r], f2v[r], f3[r]);
    }
    int b = blockIdx.x >> 5;
    int n0 = (blockIdx.x & 31) * 64;
    // uint32 index of this 32-group's base, plus per-8-group offset bofs
    int bofs = (r0 & 31) >> 3;
    size_t grp32 = ((size_t)(n0 + (r0 & ~31))) >> 1;
    #pragma unroll
    for (int e = 0; e < 4; e++) {
        const float* fe = (e == 0) ? f0 : (e == 1) ? f1v : (e == 2) ? f2v : f3;
        uint32_t* dst = g_WhT32 + (((size_t)b * FF + c0 + e) * NN >> 1) + grp32 + bofs;
        #pragma unroll
        for (int s = 0; s < 4; s++)
            dst[4 * s] = pkhf(fe[2 * s], fe[2 * s + 1]);
    }
}

// ===================== k2: f1,f2 + exp tables (j-tables sigma-permuted) ======
__global__ void k2_scores(const float* __restrict__ h) {
    int row = blockIdx.x * 8 + (threadIdx.x >> 5);
    int lane = threadIdx.x & 31;
    float s1 = 0.f, s2 = 0.f;
    #pragma unroll
    for (int q = 0; q < 4; q++) {
        float hv = h[(size_t)row * FF + lane + 32 * q];
        s1 += hv * g_wa[lane + 32 * q];
        s2 += hv * g_wa[FF + lane + 32 * q];
    }
    #pragma unroll
    for (int o = 16; o; o >>= 1) {
        s1 += __shfl_xor_sync(0xFFFFFFFFu, s1, o);
        s2 += __shfl_xor_sync(0xFFFFFFFFu, s2, o);
    }
    if (lane == 0) {
        g_f1[row]  = s1;
        g_E1p[row] = expf(s1);
        g_E1n[row] = expf(0.2f * s1);
        int prow = (row & ~(NN - 1)) | sigma32(row & (NN - 1));
        g_f2[prow]  = s2;
        g_E2p[prow] = expf(s2);
        g_E2n[prow] = expf(0.2f * s2);
    }
}

// ===================== k3: pipelined f16 mma masked-attention GEMM ===========
// 512 threads / 16 warps. smem (uint32/float units):
// whts0@0(4608), whts1@4608, u0@9216, u1@13824, ftab@18432, eptab@20480,
// entab@22528, z@24576, bias@24704; total 24832 words
#define K3_SMEM (24832 * 4)

// build masked-exp U for one (row, 16-phys-j group); emit 8 half2 words
__device__ __forceinline__ float build_u(const float4* av, const float* ftab,
                                         const float* eptab, const float* entab,
                                         int joff, float rf1, float rEp, float rEn,
                                         uint32_t* drow) {
    uint32_t pk[8];
    float zz = 0.f;
    #pragma unroll
    for (int g = 0; g < 4; g++) {
        float4 f = *(const float4*)&ftab[joff + g * 4];
        float4 p = *(const float4*)&eptab[joff + g * 4];
        float4 n = *(const float4*)&entab[joff + g * 4];
        float4 a = av[g];
        float u[4];
        #pragma unroll
        for (int e = 0; e < 4; e++) {
            float s = rf1 + (&f.x)[e];
            float v = (s > 0.f) ? (rEp * (&p.x)[e]) : (rEn * (&n.x)[e]);
            u[e] = ((&a.x)[e] > 0.f) ? v : 0.f;
        }
        pk[2 * g]     = pkhf(u[0], u[1]);
        pk[2 * g + 1] = pkhf(u[2], u[3]);
    }
    #pragma unroll
    for (int q = 0; q < 8; q++) {  // sum the fp16-rounded values (exact unpack)
        float2 f2u = __half22float2(*reinterpret_cast<__half2*>(&pk[q]));
        zz += f2u.x + f2u.y;
    }
    *(uint4*)&drow[0] = make_uint4(pk[0], pk[1], pk[2], pk[3]);
    *(uint4*)&drow[4] = make_uint4(pk[4], pk[5], pk[6], pk[7]);
    return zz;
}

__global__ __launch_bounds__(512, 1) void k3_main(const float* __restrict__ bias,
                                                  float* __restrict__ out) {
    extern __shared__ uint32_t smw[];
    uint32_t* whts[2] = { smw, smw + 4608 };
    uint32_t* u_s[2]  = { smw + 9216, smw + 13824 };
    float* ftab    = (float*)(smw + 18432);
    float* eptab   = (float*)(smw + 20480);
    float* entab   = (float*)(smw + 22528);
    float* z_s     = (float*)(smw + 24576);
    float* bias_s  = (float*)(smw + 24704);

    const int tid = threadIdx.x;
    const int b = blockIdx.x >> 4;
    const int i0 = (blockIdx.x & 15) * 128;
    const int bn = b * NN;

    // ---- per-CTA tables (whole permuted 2048-j range, loaded once) ----
    {
        int i = tid * 4;
        *(float4*)&ftab[i]  = *(const float4*)&g_f2[bn + i];
        *(float4*)&eptab[i] = *(const float4*)&g_E2p[bn + i];
        *(float4*)&entab[i] = *(const float4*)&g_E2n[bn + i];
    }
    if (tid < 128) bias_s[tid] = bias[tid];

    // ---- builder identity: one row, one 16-phys-j group of the 64-j tile ----
    const int brow = tid >> 2;
    const int bh = tid & 3;
    const float rf1 = g_f1[bn + i0 + brow];
    const float rEp = g_E1p[bn + i0 + brow];
    const float rEn = g_E1n[bn + i0 + brow];
    const float* adjp = g_adjP + (size_t)(i0 + brow) * NN + bh * 16;
    const int doff = brow * SRD32 + bh * 8;

    // ---- WhT cp.async staging identity: row tid>>2, quad tid&3 ----
    const uint32_t* whp = g_WhT32 + (((size_t)b * FF + (tid >> 2)) * NN >> 1) + (tid & 3) * 4;
    const int sdo = (tid >> 2) * SRD32 + (tid & 3) * 4;
    const uint32_t wdst[2] = { smem_u32(whts[0]) + sdo * 4, smem_u32(whts[1]) + sdo * 4 };

    // ---- mma identity: 16 warps as 4(M) x 4(N); warp tile 32 x 32 ----
    const int lane = tid & 31, wid = tid >> 5;
    const int mg = wid >> 2, ng = wid & 3;
    const int l4 = lane >> 2, lm = lane & 3;

    float acc[2][4][4] = {};
    float zpart = 0.f;
    float4 av[4];

    __syncthreads();  // tables staged

    // ---- prologue: stage tile 0 ----
    #pragma unroll
    for (int ch = 0; ch < 2; ch++) cp_async16(wdst[0] + ch * 64, whp + ch * 16);
    asm volatile("cp.async.commit_group;");
    #pragma unroll
    for (int k = 0; k < 4; k++) av[k] = ((const float4*)adjp)[k];
    zpart += build_u(av, ftab, eptab, entab, bh * 16, rf1, rEp, rEn, u_s[0] + doff);
    asm volatile("cp.async.wait_group 0;" ::: "memory");
    __syncthreads();

    for (int t = 0; t < 32; t++) {
        const int cur = t & 1, nxt = cur ^ 1;
        const int jb2 = (t + 1) * TJ;

        // ---- issue next tile's loads (async) ----
        if (t < 31) {
            #pragma unroll
            for (int ch = 0; ch < 2; ch++)
                cp_async16(wdst[nxt] + ch * 64, whp + (jb2 >> 1) + ch * 16);
            asm volatile("cp.async.commit_group;");
            #pragma unroll
            for (int k = 0; k < 4; k++) av[k] = ((const float4*)(adjp + jb2))[k];
        }

        // ---- mma(t): 2 k32 chunks x 2 k16 steps; dual-step LDS.128 frags ----
        const uint32_t* wb = whts[cur];
        const uint32_t* ub = u_s[cur];
        #pragma unroll
        for (int ch = 0; ch < 2; ch++) {
            const int kc = ch * 16 + lm * 4;
            uint4 bv[4];
            #pragma unroll
            for (int ni = 0; ni < 4; ni++)
                bv[ni] = *(const uint4*)&wb[(ng * 32 + ni * 8 + l4) * SRD32 + kc];
            uint4 alo[2], ahi[2];
            #pragma unroll
            for (int mi = 0; mi < 2; mi++) {
                int row = mg * 32 + mi * 16 + l4;
                alo[mi] = *(const uint4*)&ub[row * SRD32 + kc];
                ahi[mi] = *(const uint4*)&ub[(row + 8) * SRD32 + kc];
            }
            #pragma unroll
            for (int mi = 0; mi < 2; mi++)    // k16 step 0: pairs tg, tg+4
                #pragma unroll
                for (int ni = 0; ni < 4; ni++)
                    mma16(acc[mi][ni], alo[mi].x, ahi[mi].x, alo[mi].y, ahi[mi].y,
                          bv[ni].x, bv[ni].y);
            #pragma unroll
            for (int mi = 0; mi < 2; mi++)    // k16 step 1: pairs tg+8, tg+12
                #pragma unroll
                for (int ni = 0; ni < 4; ni++)
                    mma16(acc[mi][ni], alo[mi].z, ahi[mi].z, alo[mi].w, ahi[mi].w,
                          bv[ni].z, bv[ni].w);
        }

        // ---- convert + store U(t+1) ----
        if (t < 31)
            zpart += build_u(av, ftab, eptab, entab, jb2 + bh * 16,
                             rf1, rEp, rEn, u_s[nxt] + doff);

        asm volatile("cp.async.wait_group 0;" ::: "memory");
        __syncthreads();
    }

    // ---- Z finalize: 4 group-threads per row are adjacent lanes ----
    zpart += __shfl_xor_sync(0xFFFFFFFFu, zpart, 1);
    zpart += __shfl_xor_sync(0xFFFFFFFFu, zpart, 2);
    if (bh == 0) z_s[brow] = zpart;
    __syncthreads();

    // ---- epilogue: 1/Z, +bias, ELU, store from fragments ----
    #pragma unroll
    for (int mi = 0; mi < 2; mi++) {
        const int r0 = mg * 32 + mi * 16 + l4;
        const float iz0 = 1.0f / z_s[r0];
        const float iz1 = 1.0f / z_s[r0 + 8];
        float* o0 = out + ((size_t)(bn + i0 + r0)) * FF;
        float* o1 = o0 + (size_t)8 * FF;
        #pragma unroll
        for (int ni = 0; ni < 4; ni++) {
            const int col = ng * 32 + ni * 8 + 2 * lm;
            const float b0 = bias_s[col], b1 = bias_s[col + 1];
            float x0 = acc[mi][ni][0] * iz0 + b0;
            float x1 = acc[mi][ni][1] * iz0 + b1;
            float x2 = acc[mi][ni][2] * iz1 + b0;
            float x3 = acc[mi][ni][3] * iz1 + b1;
            x0 = (x0 > 0.f) ? x0 : expm1f(x0);
            x1 = (x1 > 0.f) ? x1 : expm1f(x1);
            x2 = (x2 > 0.f) ? x2 : expm1f(x2);
            x3 = (x3 > 0.f) ? x3 : expm1f(x3);
            *(float2*)&o0[col] = make_float2(x0, x1);
            *(float2*)&o1[col] = make_float2(x2, x3);
        }
    }
}

// ============================== launch ==============================
extern "C" void kernel_launch(void* const* d_in, const int* in_sizes, int n_in,
                              void* d_out, int out_size) {
    const float* h    = (const float*)d_in[0];
    const float* adj  = (const float*)d_in[1];
    const float* W    = (const float*)d_in[2];
    const float* a    = (const float*)d_in[3];
    const float* bias = (const float*)d_in[4];
    float* out = (float*)d_out;

    const int smem1 = 65536 + 32768;
    cudaFuncSetAttribute(k1_gemm, cudaFuncAttributeMaxDynamicSharedMemorySize, smem1);
    cudaFuncSetAttribute(k3_main, cudaFuncAttributeMaxDynamicSharedMemorySize, K3_SMEM);

    k_adjP<<<NN * NN / 4 / 256, 256>>>(adj);
    k0_wa<<<1, 128>>>(W, a);
    k1_gemm<<<(BB * NN) / 64, 256, smem1>>>(h, W);
    k2_scores<<<(BB * NN) / 8, 256>>>(h);
    k3_main<<<128, 512, K3_SMEM>>>(bias, out);
}

// round 10
// speedup vs baseline: 2.5609x; 1.1097x over previous
#include <cuda_runtime.h>
#include <cuda_fp16.h>
#include <math.h>
#include <stdint.h>

// Problem constants
#define BB 8
#define NN 2048
#define FF 128
#define TJ 64            // j-tile per iteration in k3
#define SRD32 36         // smem row stride (uint32): conflict-free LDS.128/STS.128

typedef unsigned long long ull;

// -------- device scratch --------
__device__ uint32_t g_WhT32[BB * FF * NN / 2];  // [b][f][j/2] half2, sigma-permuted, 4MB
__device__ uint8_t g_adjP8[NN * NN];            // sigma-permuted adjacency mask, 4MB
__device__ float g_wa[2 * FF];
__device__ float g_f1[BB * NN];
__device__ float g_f2[BB * NN];                 // j-permuted
__device__ float g_E1p[BB * NN];
__device__ float g_E1n[BB * NN];
__device__ float g_E2p[BB * NN];                // j-permuted
__device__ float g_E2n[BB * NN];                // j-permuted

// ======================= helpers =======================
__device__ __forceinline__ ull pk2(float lo, float hi) {
    ull d;
    asm("mov.b64 %0, {%1, %2};" : "=l"(d) : "r"(__float_as_uint(lo)), "r"(__float_as_uint(hi)));
    return d;
}
__device__ __forceinline__ void upk2(ull v, float& lo, float& hi) {
    unsigned a, b;
    asm("mov.b64 {%0, %1}, %2;" : "=r"(a), "=r"(b) : "l"(v));
    lo = __uint_as_float(a); hi = __uint_as_float(b);
}
__device__ __forceinline__ ull pfma(ull a, ull b, ull c) {
    ull d;
    asm("fma.rn.f32x2 %0, %1, %2, %3;" : "=l"(d) : "l"(a), "l"(b), "l"(c));
    return d;
}
// pack two f32 -> half2 (lo -> low half, hi -> high half)
__device__ __forceinline__ uint32_t pkhf(float lo, float hi) {
    __half2 t = __floats2half2_rn(lo, hi);
    return *reinterpret_cast<uint32_t*>(&t);
}
// m16n8k16 f16 MMA, fp32 accumulate (sm_80+ PTX, valid on base sm_103)
__device__ __forceinline__ void mma16(float* c, uint32_t a0, uint32_t a1, uint32_t a2,
                                      uint32_t a3, uint32_t b0, uint32_t b1) {
    asm volatile(
        "mma.sync.aligned.m16n8k16.row.col.f32.f16.f16.f32 "
        "{%0,%1,%2,%3}, {%4,%5,%6,%7}, {%8,%9}, {%0,%1,%2,%3};"
        : "+f"(c[0]), "+f"(c[1]), "+f"(c[2]), "+f"(c[3])
        : "r"(a0), "r"(a1), "r"(a2), "r"(a3), "r"(b0), "r"(b1));
}
__device__ __forceinline__ uint32_t smem_u32(const void* p) {
    uint32_t a;
    asm("{ .reg .u64 t; cvta.to.shared.u64 t, %1; cvt.u32.u64 %0, t; }" : "=r"(a) : "l"(p));
    return a;
}
__device__ __forceinline__ void cp_async16(uint32_t dst, const void* src) {
    asm volatile("cp.async.cg.shared.global [%0], [%1], 16;" :: "r"(dst), "l"(src));
}
// sigma: physical position of logical j within its 32-group
__device__ __forceinline__ int sigma32(int j) {
    return (j & ~31) | (8 * ((j >> 1) & 3) + 2 * ((j >> 3) & 3) + (j & 1));
}

// ===================== k_adjP: permute adjacency to sigma order, byte mask ===
__global__ void k_adjP(const float* __restrict__ adj) {
    size_t idx = ((size_t)blockIdx.x * 256 + threadIdx.x) * 4;
    float4 v = *(const float4*)&adj[idx];
    int jc = (int)(idx & (NN - 1));
    size_t rowbase = idx & ~(size_t)(NN - 1);
    #pragma unroll
    for (int e = 0; e < 4; e++)
        g_adjP8[rowbase + sigma32(jc + e)] = ((&v.x)[e] > 0.f) ? 1u : 0u;
}

// ===================== k0: wa = W @ a1, W @ a2 =====================
__global__ void k0_wa(const float* __restrict__ W, const float* __restrict__ a) {
    int f = threadIdx.x;
    float s1 = 0.f, s2 = 0.f;
    #pragma unroll 8
    for (int o = 0; o < FF; o++) {
        float w = W[f * FF + o];
        s1 += w * a[o];
        s2 += w * a[FF + o];
    }
    g_wa[f] = s1;
    g_wa[FF + f] = s2;
}

// ===================== k1: WhT = (h @ W)^T, half2, sigma-permuted ============
__global__ __launch_bounds__(256, 2) void k1_gemm(const float* __restrict__ h,
                                                  const float* __restrict__ W) {
    extern __shared__ char smem1[];
    float* Ws = (float*)smem1;            // 64KB
    float* hs = (float*)(smem1 + 65536);  // 32KB

    int tid = threadIdx.x;
    const float* hb = h + (size_t)blockIdx.x * 64 * FF;

    #pragma unroll
    for (int i = tid * 4; i < FF * FF; i += 1024)
        *(float4*)&Ws[i] = *(const float4*)&W[i];
    #pragma unroll
    for (int i = tid * 4; i < 64 * FF; i += 1024)
        *(float4*)&hs[i] = *(const float4*)&hb[i];
    __syncthreads();

    int c0 = (tid & 31) * 4;
    int r0 = (tid >> 5) * 8;      // 8 consecutive j-rows
    ull accA[8], accB[8];
    #pragma unroll
    for (int r = 0; r < 8; r++) { accA[r] = 0ULL; accB[r] = 0ULL; }

    for (int k = 0; k < FF; k++) {
        float4 w = *(float4*)&Ws[k * FF + c0];
        ull wA = pk2(w.x, w.y), wB = pk2(w.z, w.w);
        #pragma unroll
        for (int r = 0; r < 8; r++) {
            float hv = hs[(r0 + r) * FF + k];
            ull hd = pk2(hv, hv);
            accA[r] = pfma(hd, wA, accA[r]);
            accB[r] = pfma(hd, wB, accB[r]);
        }
    }

    float f0[8], f1v[8], f2v[8], f3[8];
    #pragma unroll
    for (int r = 0; r < 8; r++) {
        upk2(accA[r], f0[r], f1v[r]);
        upk2(accB[r], f2v[r], f3[r]);
    }
    int b = blockIdx.x >> 5;
    int n0 = (blockIdx.x & 31) * 64;
    int bofs = (r0 & 31) >> 3;
    size_t grp32 = ((size_t)(n0 + (r0 & ~31))) >> 1;
    #pragma unroll
    for (int e = 0; e < 4; e++) {
        const float* fe = (e == 0) ? f0 : (e == 1) ? f1v : (e == 2) ? f2v : f3;
        uint32_t* dst = g_WhT32 + (((size_t)b * FF + c0 + e) * NN >> 1) + grp32 + bofs;
        #pragma unroll
        for (int s = 0; s < 4; s++)
            dst[4 * s] = pkhf(fe[2 * s], fe[2 * s + 1]);
    }
}

// ===================== k2: f1,f2 + exp tables (j-tables sigma-permuted) ======
__global__ void k2_scores(const float* __restrict__ h) {
    int row = blockIdx.x * 8 + (threadIdx.x >> 5);
    int lane = threadIdx.x & 31;
    float s1 = 0.f, s2 = 0.f;
    #pragma unroll
    for (int q = 0; q < 4; q++) {
        float hv = h[(size_t)row * FF + lane + 32 * q];
        s1 += hv * g_wa[lane + 32 * q];
        s2 += hv * g_wa[FF + lane + 32 * q];
    }
    #pragma unroll
    for (int o = 16; o; o >>= 1) {
        s1 += __shfl_xor_sync(0xFFFFFFFFu, s1, o);
        s2 += __shfl_xor_sync(0xFFFFFFFFu, s2, o);
    }
    if (lane == 0) {
        g_f1[row]  = s1;
        g_E1p[row] = expf(s1);
        g_E1n[row] = expf(0.2f * s1);
        int prow = (row & ~(NN - 1)) | sigma32(row & (NN - 1));
        g_f2[prow]  = s2;
        g_E2p[prow] = expf(s2);
        g_E2n[prow] = expf(0.2f * s2);
    }
}

// ===================== k3: pipelined f16 mma masked-attention GEMM ===========
// 256 threads / 8 warps / 64 i-rows per CTA; 2 CTAs per SM; grid 256.
// smem (uint32 words): whts0@0(4608), whts1@4608, u0@9216(2304), u1@11520,
// ftab@13824, eptab@15872, entab@17920, z@19968(64), bias@20032(128); tot 20160
#define K3_SMEM (20160 * 4)

// build masked-exp U for one (row, 16-phys-j group); byte mask; emit 8 half2
__device__ __forceinline__ float build_u(uint4 am, const float* ftab,
                                         const float* eptab, const float* entab,
                                         int joff, float rf1, float rEp, float rEn,
                                         uint32_t* drow) {
    uint32_t mw[4] = { am.x, am.y, am.z, am.w };
    uint32_t pk[8];
    float zz = 0.f;
    #pragma unroll
    for (int g = 0; g < 4; g++) {
        float4 f = *(const float4*)&ftab[joff + g * 4];
        float4 p = *(const float4*)&eptab[joff + g * 4];
        float4 n = *(const float4*)&entab[joff + g * 4];
        float u[4];
        #pragma unroll
        for (int e = 0; e < 4; e++) {
            float s = rf1 + (&f.x)[e];
            float v = (s > 0.f) ? (rEp * (&p.x)[e]) : (rEn * (&n.x)[e]);
            u[e] = ((mw[g] >> (8 * e)) & 0xFFu) ? v : 0.f;
        }
        pk[2 * g]     = pkhf(u[0], u[1]);
        pk[2 * g + 1] = pkhf(u[2], u[3]);
    }
    #pragma unroll
    for (int q = 0; q < 8; q++) {  // sum the fp16-rounded values
        float2 f2u = __half22float2(*reinterpret_cast<__half2*>(&pk[q]));
        zz += f2u.x + f2u.y;
    }
    *(uint4*)&drow[0] = make_uint4(pk[0], pk[1], pk[2], pk[3]);
    *(uint4*)&drow[4] = make_uint4(pk[4], pk[5], pk[6], pk[7]);
    return zz;
}

__global__ __launch_bounds__(256, 2) void k3_main(const float* __restrict__ bias,
                                                  float* __restrict__ out) {
    extern __shared__ uint32_t smw[];
    uint32_t* whts[2] = { smw, smw + 4608 };
    uint32_t* u_s[2]  = { smw + 9216, smw + 11520 };
    float* ftab    = (float*)(smw + 13824);
    float* eptab   = (float*)(smw + 15872);
    float* entab   = (float*)(smw + 17920);
    float* z_s     = (float*)(smw + 19968);
    float* bias_s  = (float*)(smw + 20032);

    const int tid = threadIdx.x;
    const int b = blockIdx.x >> 5;
    const int i0 = (blockIdx.x & 31) * 64;
    const int bn = b * NN;

    // ---- per-CTA tables (whole permuted 2048-j range, loaded once) ----
    #pragma unroll
    for (int i = tid * 4; i < NN; i += 1024) {
        *(float4*)&ftab[i]  = *(const float4*)&g_f2[bn + i];
        *(float4*)&eptab[i] = *(const float4*)&g_E2p[bn + i];
        *(float4*)&entab[i] = *(const float4*)&g_E2n[bn + i];
    }
    if (tid < 128) bias_s[tid] = bias[tid];

    // ---- builder identity: one row, one 16-phys-j group of the 64-j tile ----
    const int brow = tid >> 2;        // 0..63
    const int bh = tid & 3;
    const float rf1 = g_f1[bn + i0 + brow];
    const float rEp = g_E1p[bn + i0 + brow];
    const float rEn = g_E1n[bn + i0 + brow];
    const uint8_t* adjp = g_adjP8 + (size_t)(i0 + brow) * NN + bh * 16;
    const int doff = brow * SRD32 + bh * 8;

    // ---- WhT cp.async staging identity: row tid>>1, half tid&1 (16 words) ----
    const uint32_t* whp = g_WhT32 + (((size_t)b * FF + (tid >> 1)) * NN >> 1) + (tid & 1) * 16;
    const int sdo = (tid >> 1) * SRD32 + (tid & 1) * 16;
    const uint32_t wdst[2] = { smem_u32(whts[0]) + sdo * 4, smem_u32(whts[1]) + sdo * 4 };

    // ---- mma identity: 8 warps as 2(M) x 4(N); warp tile 32 x 32 ----
    const int lane = tid & 31, wid = tid >> 5;
    const int mg = wid >> 2, ng = wid & 3;
    const int l4 = lane >> 2, lm = lane & 3;

    float acc[2][4][4] = {};
    float zpart = 0.f;
    uint4 am;

    __syncthreads();  // tables staged

    // ---- prologue: stage tile 0 ----
    #pragma unroll
    for (int ch = 0; ch < 4; ch++) cp_async16(wdst[0] + ch * 16, whp + ch * 4);
    asm volatile("cp.async.commit_group;");
    am = *(const uint4*)adjp;
    zpart += build_u(am, ftab, eptab, entab, bh * 16, rf1, rEp, rEn, u_s[0] + doff);
    asm volatile("cp.async.wait_group 0;" ::: "memory");
    __syncthreads();

    for (int t = 0; t < 32; t++) {
        const int cur = t & 1, nxt = cur ^ 1;
        const int jb2 = (t + 1) * TJ;

        // ---- issue next tile's loads (async) ----
        if (t < 31) {
            #pragma unroll
            for (int ch = 0; ch < 4; ch++)
                cp_async16(wdst[nxt] + ch * 16, whp + (jb2 >> 1) + ch * 4);
            asm volatile("cp.async.commit_group;");
            am = *(const uint4*)(adjp + jb2);
        }

        // ---- mma(t): 2 k32 chunks x 2 k16 steps; dual-step LDS.128 frags ----
        const uint32_t* wb = whts[cur];
        const uint32_t* ub = u_s[cur];
        #pragma unroll
        for (int ch = 0; ch < 2; ch++) {
            const int kc = ch * 16 + lm * 4;
            uint4 bv[4];
            #pragma unroll
            for (int ni = 0; ni < 4; ni++)
                bv[ni] = *(const uint4*)&wb[(ng * 32 + ni * 8 + l4) * SRD32 + kc];
            uint4 alo[2], ahi[2];
            #pragma unroll
            for (int mi = 0; mi < 2; mi++) {
                int row = mg * 32 + mi * 16 + l4;
                alo[mi] = *(const uint4*)&ub[row * SRD32 + kc];
                ahi[mi] = *(const uint4*)&ub[(row + 8) * SRD32 + kc];
            }
            #pragma unroll
            for (int mi = 0; mi < 2; mi++)    // k16 step 0
                #pragma unroll
                for (int ni = 0; ni < 4; ni++)
                    mma16(acc[mi][ni], alo[mi].x, ahi[mi].x, alo[mi].y, ahi[mi].y,
                          bv[ni].x, bv[ni].y);
            #pragma unroll
            for (int mi = 0; mi < 2; mi++)    // k16 step 1
                #pragma unroll
                for (int ni = 0; ni < 4; ni++)
                    mma16(acc[mi][ni], alo[mi].z, ahi[mi].z, alo[mi].w, ahi[mi].w,
                          bv[ni].z, bv[ni].w);
        }

        // ---- convert + store U(t+1) ----
        if (t < 31)
            zpart += build_u(am, ftab, eptab, entab, jb2 + bh * 16,
                             rf1, rEp, rEn, u_s[nxt] + doff);

        asm volatile("cp.async.wait_group 0;" ::: "memory");
        __syncthreads();
    }

    // ---- Z finalize: 4 group-threads per row are adjacent lanes ----
    zpart += __shfl_xor_sync(0xFFFFFFFFu, zpart, 1);
    zpart += __shfl_xor_sync(0xFFFFFFFFu, zpart, 2);
    if (bh == 0) z_s[brow] = zpart;
    __syncthreads();

    // ---- epilogue: 1/Z, +bias, ELU, store from fragments ----
    #pragma unroll
    for (int mi = 0; mi < 2; mi++) {
        const int r0 = mg * 32 + mi * 16 + l4;
        const float iz0 = 1.0f / z_s[r0];
        const float iz1 = 1.0f / z_s[r0 + 8];
        float* o0 = out + ((size_t)(bn + i0 + r0)) * FF;
        float* o1 = o0 + (size_t)8 * FF;
        #pragma unroll
        for (int ni = 0; ni < 4; ni++) {
            const int col = ng * 32 + ni * 8 + 2 * lm;
            const float b0 = bias_s[col], b1 = bias_s[col + 1];
            float x0 = acc[mi][ni][0] * iz0 + b0;
            float x1 = acc[mi][ni][1] * iz0 + b1;
            float x2 = acc[mi][ni][2] * iz1 + b0;
            float x3 = acc[mi][ni][3] * iz1 + b1;
            x0 = (x0 > 0.f) ? x0 : expm1f(x0);
            x1 = (x1 > 0.f) ? x1 : expm1f(x1);
            x2 = (x2 > 0.f) ? x2 : expm1f(x2);
            x3 = (x3 > 0.f) ? x3 : expm1f(x3);
            *(float2*)&o0[col] = make_float2(x0, x1);
            *(float2*)&o1[col] = make_float2(x2, x3);
        }
    }
}

// ============================== launch ==============================
extern "C" void kernel_launch(void* const* d_in, const int* in_sizes, int n_in,
                              void* d_out, int out_size) {
    const float* h    = (const float*)d_in[0];
    const float* adj  = (const float*)d_in[1];
    const float* W    = (const float*)d_in[2];
    const float* a    = (const float*)d_in[3];
    const float* bias = (const float*)d_in[4];
    float* out = (float*)d_out;

    const int smem1 = 65536 + 32768;
    cudaFuncSetAttribute(k1_gemm, cudaFuncAttributeMaxDynamicSharedMemorySize, smem1);
    cudaFuncSetAttribute(k3_main, cudaFuncAttributeMaxDynamicSharedMemorySize, K3_SMEM);

    k_adjP<<<NN * NN / 4 / 256, 256>>>(adj);
    k0_wa<<<1, 128>>>(W, a);
    k1_gemm<<<(BB * NN) / 64, 256, smem1>>>(h, W);
    k2_scores<<<(BB * NN) / 8, 256>>>(h);
    k3_main<<<256, 256, K3_SMEM>>>(bias, out);
}

// round 11
// speedup vs baseline: 2.9868x; 1.1663x over previous
#include <cuda_runtime.h>
#include <cuda_fp16.h>
#include <math.h>
#include <stdint.h>

// Problem constants
#define BB 8
#define NN 2048
#define FF 128
#define TJ 64            // j-tile per iteration in k3
#define SRD32 48         // smem row stride (uint32): quad-stride 12 = 4 mod 8 -> conflict-free

typedef unsigned long long ull;

// -------- device scratch --------
__device__ uint32_t g_WhT32[BB * FF * NN / 2];  // [b][f][j/2] half2, sigma-permuted, 4MB
__device__ uint8_t g_adjP8[NN * NN];            // sigma-permuted adjacency mask, 4MB
__device__ float g_wa[2 * FF];
__device__ float g_f1[BB * NN];
__device__ float g_f2[BB * NN];                 // j-permuted
__device__ float g_E1p[BB * NN];
__device__ float g_E1n[BB * NN];
__device__ uint32_t g_E2h2[BB * NN];            // j-permuted, half2(E2p, E2n)

// ======================= helpers =======================
__device__ __forceinline__ ull pk2(float lo, float hi) {
    ull d;
    asm("mov.b64 %0, {%1, %2};" : "=l"(d) : "r"(__float_as_uint(lo)), "r"(__float_as_uint(hi)));
    return d;
}
__device__ __forceinline__ void upk2(ull v, float& lo, float& hi) {
    unsigned a, b;
    asm("mov.b64 {%0, %1}, %2;" : "=r"(a), "=r"(b) : "l"(v));
    lo = __uint_as_float(a); hi = __uint_as_float(b);
}
__device__ __forceinline__ ull pfma(ull a, ull b, ull c) {
    ull d;
    asm("fma.rn.f32x2 %0, %1, %2, %3;" : "=l"(d) : "l"(a), "l"(b), "l"(c));
    return d;
}
// pack two f32 -> half2 (lo -> low half, hi -> high half)
__device__ __forceinline__ uint32_t pkhf(float lo, float hi) {
    __half2 t = __floats2half2_rn(lo, hi);
    return *reinterpret_cast<uint32_t*>(&t);
}
// m16n8k16 f16 MMA, fp32 accumulate
__device__ __forceinline__ void mma16(float* c, uint32_t a0, uint32_t a1, uint32_t a2,
                                      uint32_t a3, uint32_t b0, uint32_t b1) {
    asm volatile(
        "mma.sync.aligned.m16n8k16.row.col.f32.f16.f16.f32 "
        "{%0,%1,%2,%3}, {%4,%5,%6,%7}, {%8,%9}, {%0,%1,%2,%3};"
        : "+f"(c[0]), "+f"(c[1]), "+f"(c[2]), "+f"(c[3])
        : "r"(a0), "r"(a1), "r"(a2), "r"(a3), "r"(b0), "r"(b1));
}
__device__ __forceinline__ uint32_t smem_u32(const void* p) {
    uint32_t a;
    asm("{ .reg .u64 t; cvta.to.shared.u64 t, %1; cvt.u32.u64 %0, t; }" : "=r"(a) : "l"(p));
    return a;
}
__device__ __forceinline__ void cp_async16(uint32_t dst, const void* src) {
    asm volatile("cp.async.cg.shared.global [%0], [%1], 16;" :: "r"(dst), "l"(src));
}
// sigma: physical position of logical j within its 32-group
__device__ __forceinline__ int sigma32(int j) {
    return (j & ~31) | (8 * ((j >> 1) & 3) + 2 * ((j >> 3) & 3) + (j & 1));
}

// ===================== k_adjP: permute adjacency to sigma order, byte mask ===
__global__ void k_adjP(const float* __restrict__ adj) {
    size_t idx = ((size_t)blockIdx.x * 256 + threadIdx.x) * 4;
    float4 v = *(const float4*)&adj[idx];
    int jc = (int)(idx & (NN - 1));
    size_t rowbase = idx & ~(size_t)(NN - 1);
    #pragma unroll
    for (int e = 0; e < 4; e++)
        g_adjP8[rowbase + sigma32(jc + e)] = ((&v.x)[e] > 0.f) ? 1u : 0u;
}

// ===================== k0: wa = W @ a1, W @ a2 =====================
__global__ void k0_wa(const float* __restrict__ W, const float* __restrict__ a) {
    int f = threadIdx.x;
    float s1 = 0.f, s2 = 0.f;
    #pragma unroll 8
    for (int o = 0; o < FF; o++) {
        float w = W[f * FF + o];
        s1 += w * a[o];
        s2 += w * a[FF + o];
    }
    g_wa[f] = s1;
    g_wa[FF + f] = s2;
}

// ===================== k1: WhT = (h @ W)^T, half2, sigma-permuted ============
__global__ __launch_bounds__(256, 2) void k1_gemm(const float* __restrict__ h,
                                                  const float* __restrict__ W) {
    extern __shared__ char smem1[];
    float* Ws = (float*)smem1;            // 64KB
    float* hs = (float*)(smem1 + 65536);  // 32KB

    int tid = threadIdx.x;
    const float* hb = h + (size_t)blockIdx.x * 64 * FF;

    #pragma unroll
    for (int i = tid * 4; i < FF * FF; i += 1024)
        *(float4*)&Ws[i] = *(const float4*)&W[i];
    #pragma unroll
    for (int i = tid * 4; i < 64 * FF; i += 1024)
        *(float4*)&hs[i] = *(const float4*)&hb[i];
    __syncthreads();

    int c0 = (tid & 31) * 4;
    int r0 = (tid >> 5) * 8;      // 8 consecutive j-rows
    ull accA[8], accB[8];
    #pragma unroll
    for (int r = 0; r < 8; r++) { accA[r] = 0ULL; accB[r] = 0ULL; }

    for (int k4 = 0; k4 < FF; k4 += 4) {
        ull wA[4], wB[4];
        #pragma unroll
        for (int s = 0; s < 4; s++) {
            float4 w = *(float4*)&Ws[(k4 + s) * FF + c0];
            wA[s] = pk2(w.x, w.y);
            wB[s] = pk2(w.z, w.w);
        }
        #pragma unroll
        for (int r = 0; r < 8; r++) {
            float4 hv = *(float4*)&hs[(r0 + r) * FF + k4];
            ull h0 = pk2(hv.x, hv.x), h1 = pk2(hv.y, hv.y);
            ull h2 = pk2(hv.z, hv.z), h3 = pk2(hv.w, hv.w);
            accA[r] = pfma(h0, wA[0], accA[r]);
            accB[r] = pfma(h0, wB[0], accB[r]);
            accA[r] = pfma(h1, wA[1], accA[r]);
            accB[r] = pfma(h1, wB[1], accB[r]);
            accA[r] = pfma(h2, wA[2], accA[r]);
            accB[r] = pfma(h2, wB[2], accB[r]);
            accA[r] = pfma(h3, wA[3], accA[r]);
            accB[r] = pfma(h3, wB[3], accB[r]);
        }
    }

    float f0[8], f1v[8], f2v[8], f3[8];
    #pragma unroll
    for (int r = 0; r < 8; r++) {
        upk2(accA[r], f0[r], f1v[r]);
        upk2(accB[r], f2v[r], f3[r]);
    }
    int b = blockIdx.x >> 5;
    int n0 = (blockIdx.x & 31) * 64;
    int bofs = (r0 & 31) >> 3;
    size_t grp32 = ((size_t)(n0 + (r0 & ~31))) >> 1;
    #pragma unroll
    for (int e = 0; e < 4; e++) {
        const float* fe = (e == 0) ? f0 : (e == 1) ? f1v : (e == 2) ? f2v : f3;
        uint32_t* dst = g_WhT32 + (((size_t)b * FF + c0 + e) * NN >> 1) + grp32 + bofs;
        #pragma unroll
        for (int s = 0; s < 4; s++)
            dst[4 * s] = pkhf(fe[2 * s], fe[2 * s + 1]);
    }
}

// ===================== k2: f1,f2 + exp tables (j-tables sigma-permuted) ======
__global__ void k2_scores(const float* __restrict__ h) {
    int row = blockIdx.x * 8 + (threadIdx.x >> 5);
    int lane = threadIdx.x & 31;
    float s1 = 0.f, s2 = 0.f;
    #pragma unroll
    for (int q = 0; q < 4; q++) {
        float hv = h[(size_t)row * FF + lane + 32 * q];
        s1 += hv * g_wa[lane + 32 * q];
        s2 += hv * g_wa[FF + lane + 32 * q];
    }
    #pragma unroll
    for (int o = 16; o; o >>= 1) {
        s1 += __shfl_xor_sync(0xFFFFFFFFu, s1, o);
        s2 += __shfl_xor_sync(0xFFFFFFFFu, s2, o);
    }
    if (lane == 0) {
        g_f1[row]  = s1;
        g_E1p[row] = expf(s1);
        g_E1n[row] = expf(0.2f * s1);
        int prow = (row & ~(NN - 1)) | sigma32(row & (NN - 1));
        g_f2[prow]   = s2;
        g_E2h2[prow] = pkhf(expf(s2), expf(0.2f * s2));
    }
}

// ===================== k3: pipelined f16 mma masked-attention GEMM ===========
// 256 threads / 8 warps / 64 i-rows per CTA; 2 CTAs per SM; grid 256.
// smem (uint32 words): whts0@0(6144), whts1@6144, u0@12288(3072), u1@15360,
// ftab@18432(2048), ehtab@20480(2048), z@22528(64), bias@22592(128); tot 22720
#define K3_SMEM (22720 * 4)

// build masked-exp U for one row x 8 phys-j; byte mask (u64); emit 4 half2 words
__device__ __forceinline__ float build_u8(ull m, const float* ftab,
                                          const uint32_t* ehtab, int joff,
                                          float rf1, float rEp, float rEn,
                                          uint32_t* drow) {
    uint32_t pk[4];
    float zz = 0.f;
    #pragma unroll
    for (int g = 0; g < 2; g++) {
        float4 f = *(const float4*)&ftab[joff + g * 4];
        uint4 eh = *(const uint4*)&ehtab[joff + g * 4];
        float u[4];
        #pragma unroll
        for (int e = 0; e < 4; e++) {
            float2 pe = __half22float2(*reinterpret_cast<__half2*>(&(&eh.x)[e]));
            float s = rf1 + (&f.x)[e];
            float v = (s > 0.f) ? (rEp * pe.x) : (rEn * pe.y);
            u[e] = ((m >> (8 * (g * 4 + e))) & 0xFFu) ? v : 0.f;
        }
        pk[2 * g]     = pkhf(u[0], u[1]);
        pk[2 * g + 1] = pkhf(u[2], u[3]);
    }
    #pragma unroll
    for (int q = 0; q < 4; q++) {  // sum the fp16-rounded values
        float2 f2u = __half22float2(*reinterpret_cast<__half2*>(&pk[q]));
        zz += f2u.x + f2u.y;
    }
    *(uint4*)drow = make_uint4(pk[0], pk[1], pk[2], pk[3]);
    return zz;
}

__global__ __launch_bounds__(256, 2) void k3_main(const float* __restrict__ bias,
                                                  float* __restrict__ out) {
    extern __shared__ uint32_t smw[];
    uint32_t* whts[2] = { smw, smw + 6144 };
    uint32_t* u_s[2]  = { smw + 12288, smw + 15360 };
    float* ftab      = (float*)(smw + 18432);
    uint32_t* ehtab  = smw + 20480;
    float* z_s       = (float*)(smw + 22528);
    float* bias_s    = (float*)(smw + 22592);

    const int tid = threadIdx.x;
    const int b = blockIdx.x >> 5;
    const int i0 = (blockIdx.x & 31) * 64;
    const int bn = b * NN;

    // ---- per-CTA tables (whole permuted 2048-j range, loaded once) ----
    #pragma unroll
    for (int i = tid * 4; i < NN; i += 1024) {
        *(float4*)&ftab[i] = *(const float4*)&g_f2[bn + i];
        *(uint4*)&ehtab[i] = *(const uint4*)&g_E2h2[bn + i];
    }
    if (tid < 128) bias_s[tid] = bias[tid];

    // ---- builder identity: 2 rows, one 8-phys-j octet of the 64-j tile ----
    const int rp = tid >> 3;          // 0..31 (row pair)
    const int oct = tid & 7;          // 0..7
    const int rowa = 2 * rp;
    const float rf1a = g_f1[bn + i0 + rowa],   rf1b = g_f1[bn + i0 + rowa + 1];
    const float rEpa = g_E1p[bn + i0 + rowa],  rEpb = g_E1p[bn + i0 + rowa + 1];
    const float rEna = g_E1n[bn + i0 + rowa],  rEnb = g_E1n[bn + i0 + rowa + 1];
    const uint8_t* adja = g_adjP8 + (size_t)(i0 + rowa) * NN + oct * 8;
    const uint8_t* adjb = adja + NN;
    const int doffa = rowa * SRD32 + oct * 4;
    const int doffb = doffa + SRD32;

    // ---- WhT cp.async staging identity: row tid>>1, half tid&1 (16 words) ----
    const uint32_t* whp = g_WhT32 + (((size_t)b * FF + (tid >> 1)) * NN >> 1) + (tid & 1) * 16;
    const int sdo = (tid >> 1) * SRD32 + (tid & 1) * 16;
    const uint32_t wdst[2] = { smem_u32(whts[0]) + sdo * 4, smem_u32(whts[1]) + sdo * 4 };

    // ---- mma identity: 8 warps as 2(M) x 4(N); warp tile 32 x 32 ----
    const int lane = tid & 31, wid = tid >> 5;
    const int mg = wid >> 2, ng = wid & 3;
    const int l4 = lane >> 2, lm = lane & 3;

    float acc[2][4][4] = {};
    float z0 = 0.f, z1 = 0.f;
    ull ma, mb;

    __syncthreads();  // tables staged

    // ---- prologue: stage tile 0 ----
    #pragma unroll
    for (int ch = 0; ch < 4; ch++) cp_async16(wdst[0] + ch * 16, whp + ch * 4);
    asm volatile("cp.async.commit_group;");
    ma = *(const ull*)adja;
    mb = *(const ull*)adjb;
    z0 += build_u8(ma, ftab, ehtab, oct * 8, rf1a, rEpa, rEna, u_s[0] + doffa);
    z1 += build_u8(mb, ftab, ehtab, oct * 8, rf1b, rEpb, rEnb, u_s[0] + doffb);
    asm volatile("cp.async.wait_group 0;" ::: "memory");
    __syncthreads();

    for (int t = 0; t < 32; t++) {
        const int cur = t & 1, nxt = cur ^ 1;
        const int jb2 = (t + 1) * TJ;

        // ---- issue next tile's loads (async) ----
        if (t < 31) {
            #pragma unroll
            for (int ch = 0; ch < 4; ch++)
                cp_async16(wdst[nxt] + ch * 16, whp + (jb2 >> 1) + ch * 4);
            asm volatile("cp.async.commit_group;");
            ma = *(const ull*)(adja + jb2);
            mb = *(const ull*)(adjb + jb2);
        }

        // ---- mma(t): 2 k32 chunks x 2 k16 steps; conflict-free LDS.128 frags ----
        const uint32_t* wb = whts[cur];
        const uint32_t* ub = u_s[cur];
        #pragma unroll
        for (int ch = 0; ch < 2; ch++) {
            const int kc = ch * 16 + lm * 4;
            uint4 bv[4];
            #pragma unroll
            for (int ni = 0; ni < 4; ni++)
                bv[ni] = *(const uint4*)&wb[(ng * 32 + ni * 8 + l4) * SRD32 + kc];
            uint4 alo[2], ahi[2];
            #pragma unroll
            for (int mi = 0; mi < 2; mi++) {
                int row = mg * 32 + mi * 16 + l4;
                alo[mi] = *(const uint4*)&ub[row * SRD32 + kc];
                ahi[mi] = *(const uint4*)&ub[(row + 8) * SRD32 + kc];
            }
            #pragma unroll
            for (int mi = 0; mi < 2; mi++)    // k16 step 0
                #pragma unroll
                for (int ni = 0; ni < 4; ni++)
                    mma16(acc[mi][ni], alo[mi].x, ahi[mi].x, alo[mi].y, ahi[mi].y,
                          bv[ni].x, bv[ni].y);
            #pragma unroll
            for (int mi = 0; mi < 2; mi++)    // k16 step 1
                #pragma unroll
                for (int ni = 0; ni < 4; ni++)
                    mma16(acc[mi][ni], alo[mi].z, ahi[mi].z, alo[mi].w, ahi[mi].w,
                          bv[ni].z, bv[ni].w);
        }

        // ---- convert + store U(t+1) ----
        if (t < 31) {
            z0 += build_u8(ma, ftab, ehtab, jb2 + oct * 8, rf1a, rEpa, rEna, u_s[nxt] + doffa);
            z1 += build_u8(mb, ftab, ehtab, jb2 + oct * 8, rf1b, rEpb, rEnb, u_s[nxt] + doffb);
        }

        asm volatile("cp.async.wait_group 0;" ::: "memory");
        __syncthreads();
    }

    // ---- Z finalize: 8 octet-threads per row-pair are adjacent lanes ----
    #pragma unroll
    for (int o = 1; o < 8; o <<= 1) {
        z0 += __shfl_xor_sync(0xFFFFFFFFu, z0, o);
        z1 += __shfl_xor_sync(0xFFFFFFFFu, z1, o);
    }
    if (oct == 0) { z_s[rowa] = z0; z_s[rowa + 1] = z1; }
    __syncthreads();

    // ---- epilogue: 1/Z, +bias, ELU, store from fragments ----
    #pragma unroll
    for (int mi = 0; mi < 2; mi++) {
        const int r0 = mg * 32 + mi * 16 + l4;
        const float iz0 = 1.0f / z_s[r0];
        const float iz1 = 1.0f / z_s[r0 + 8];
        float* o0 = out + ((size_t)(bn + i0 + r0)) * FF;
        float* o1 = o0 + (size_t)8 * FF;
        #pragma unroll
        for (int ni = 0; ni < 4; ni++) {
            const int col = ng * 32 + ni * 8 + 2 * lm;
            const float b0 = bias_s[col], b1 = bias_s[col + 1];
            float x0 = acc[mi][ni][0] * iz0 + b0;
            float x1 = acc[mi][ni][1] * iz0 + b1;
            float x2 = acc[mi][ni][2] * iz1 + b0;
            float x3 = acc[mi][ni][3] * iz1 + b1;
            x0 = (x0 > 0.f) ? x0 : expm1f(x0);
            x1 = (x1 > 0.f) ? x1 : expm1f(x1);
            x2 = (x2 > 0.f) ? x2 : expm1f(x2);
            x3 = (x3 > 0.f) ? x3 : expm1f(x3);
            *(float2*)&o0[col] = make_float2(x0, x1);
            *(float2*)&o1[col] = make_float2(x2, x3);
        }
    }
}

// ============================== launch ==============================
extern "C" void kernel_launch(void* const* d_in, const int* in_sizes, int n_in,
                              void* d_out, int out_size) {
    const float* h    = (const float*)d_in[0];
    const float* adj  = (const float*)d_in[1];
    const float* W    = (const float*)d_in[2];
    const float* a    = (const float*)d_in[3];
    const float* bias = (const float*)d_in[4];
    float* out = (float*)d_out;

    const int smem1 = 65536 + 32768;
    cudaFuncSetAttribute(k1_gemm, cudaFuncAttributeMaxDynamicSharedMemorySize, smem1);
    cudaFuncSetAttribute(k3_main, cudaFuncAttributeMaxDynamicSharedMemorySize, K3_SMEM);

    k_adjP<<<NN * NN / 4 / 256, 256>>>(adj);
    k0_wa<<<1, 128>>>(W, a);
    k1_gemm<<<(BB * NN) / 64, 256, smem1>>>(h, W);
    k2_scores<<<(BB * NN) / 8, 256>>>(h);
    k3_main<<<256, 256, K3_SMEM>>>(bias, out);
}

// round 12
// speedup vs baseline: 3.3932x; 1.1361x over previous
#include <cuda_runtime.h>
#include <cuda_fp16.h>
#include <math.h>
#include <stdint.h>

// Problem constants
#define BB 8
#define NN 2048
#define FF 128
#define TJ 64            // j-tile per iteration in k3
#define SRD32 48         // smem row stride (uint32): quad-stride 12 = 4 mod 8 -> conflict-free

typedef unsigned long long ull;

// -------- device scratch --------
__device__ uint32_t g_WhT32[BB * FF * NN / 2];  // [b][f][j/2] half2, sigma-permuted, 4MB
__device__ uint8_t g_adjP8[NN * NN];            // sigma-permuted adjacency mask, 4MB
__device__ float g_f1[BB * NN];
__device__ float g_f2[BB * NN];                 // j-permuted
__device__ float g_E1p[BB * NN];
__device__ float g_E1n[BB * NN];
__device__ uint32_t g_E2h2[BB * NN];            // j-permuted, half2(E2p, E2n)

// ======================= helpers =======================
__device__ __forceinline__ ull pk2(float lo, float hi) {
    ull d;
    asm("mov.b64 %0, {%1, %2};" : "=l"(d) : "r"(__float_as_uint(lo)), "r"(__float_as_uint(hi)));
    return d;
}
__device__ __forceinline__ void upk2(ull v, float& lo, float& hi) {
    unsigned a, b;
    asm("mov.b64 {%0, %1}, %2;" : "=r"(a), "=r"(b) : "l"(v));
    lo = __uint_as_float(a); hi = __uint_as_float(b);
}
__device__ __forceinline__ ull pfma(ull a, ull b, ull c) {
    ull d;
    asm("fma.rn.f32x2 %0, %1, %2, %3;" : "=l"(d) : "l"(a), "l"(b), "l"(c));
    return d;
}
// pack two f32 -> half2 (lo -> low half, hi -> high half)
__device__ __forceinline__ uint32_t pkhf(float lo, float hi) {
    __half2 t = __floats2half2_rn(lo, hi);
    return *reinterpret_cast<uint32_t*>(&t);
}
// m16n8k16 f16 MMA, fp32 accumulate
__device__ __forceinline__ void mma16(float* c, uint32_t a0, uint32_t a1, uint32_t a2,
                                      uint32_t a3, uint32_t b0, uint32_t b1) {
    asm volatile(
        "mma.sync.aligned.m16n8k16.row.col.f32.f16.f16.f32 "
        "{%0,%1,%2,%3}, {%4,%5,%6,%7}, {%8,%9}, {%0,%1,%2,%3};"
        : "+f"(c[0]), "+f"(c[1]), "+f"(c[2]), "+f"(c[3])
        : "r"(a0), "r"(a1), "r"(a2), "r"(a3), "r"(b0), "r"(b1));
}
__device__ __forceinline__ uint32_t smem_u32(const void* p) {
    uint32_t a;
    asm("{ .reg .u64 t; cvta.to.shared.u64 t, %1; cvt.u32.u64 %0, t; }" : "=r"(a) : "l"(p));
    return a;
}
__device__ __forceinline__ void cp_async16(uint32_t dst, const void* src) {
    asm volatile("cp.async.cg.shared.global [%0], [%1], 16;" :: "r"(dst), "l"(src));
}
// sigma: physical position of logical j within its 32-group
__device__ __forceinline__ int sigma32(int j) {
    return (j & ~31) | (8 * ((j >> 1) & 3) + 2 * ((j >> 3) & 3) + (j & 1));
}

// ===================== k_adjP: permute adjacency to sigma order, byte mask ===
__global__ void k_adjP(const float* __restrict__ adj) {
    size_t idx = ((size_t)blockIdx.x * 256 + threadIdx.x) * 4;
    float4 v = *(const float4*)&adj[idx];
    int jc = (int)(idx & (NN - 1));
    size_t rowbase = idx & ~(size_t)(NN - 1);
    #pragma unroll
    for (int e = 0; e < 4; e++)
        g_adjP8[rowbase + sigma32(jc + e)] = ((&v.x)[e] > 0.f) ? 1u : 0u;
}

// ===================== k1: WhT + f1/f2 + exp tables, fully fused =============
// grid 256 (8 b x 32 row-tiles of 64), 256 threads, 2 CTAs/SM
__global__ __launch_bounds__(256, 2) void k1_gemm(const float* __restrict__ h,
                                                  const float* __restrict__ W,
                                                  const float* __restrict__ a) {
    extern __shared__ char smem1[];
    float* Ws = (float*)smem1;            // 64KB (reused for score partials)
    float* hs = (float*)(smem1 + 65536);  // 32KB
    ull* part = (ull*)smem1;              // [64][32] score partials (overlay)

    int tid = threadIdx.x;
    const float* hb = h + (size_t)blockIdx.x * 64 * FF;

    #pragma unroll
    for (int i = tid * 4; i < FF * FF; i += 1024)
        *(float4*)&Ws[i] = *(const float4*)&W[i];
    #pragma unroll
    for (int i = tid * 4; i < 64 * FF; i += 1024)
        *(float4*)&hs[i] = *(const float4*)&hb[i];
    __syncthreads();

    int c0 = (tid & 31) * 4;
    int r0 = (tid >> 5) * 8;      // 8 consecutive j-rows
    ull accA[8], accB[8];
    #pragma unroll
    for (int r = 0; r < 8; r++) { accA[r] = 0ULL; accB[r] = 0ULL; }

    for (int k4 = 0; k4 < FF; k4 += 4) {
        ull wA[4], wB[4];
        #pragma unroll
        for (int s = 0; s < 4; s++) {
            float4 w = *(float4*)&Ws[(k4 + s) * FF + c0];
            wA[s] = pk2(w.x, w.y);
            wB[s] = pk2(w.z, w.w);
        }
        #pragma unroll
        for (int r = 0; r < 8; r++) {
            float4 hv = *(float4*)&hs[(r0 + r) * FF + k4];
            ull h0 = pk2(hv.x, hv.x), h1 = pk2(hv.y, hv.y);
            ull h2 = pk2(hv.z, hv.z), h3 = pk2(hv.w, hv.w);
            accA[r] = pfma(h0, wA[0], accA[r]);
            accB[r] = pfma(h0, wB[0], accB[r]);
            accA[r] = pfma(h1, wA[1], accA[r]);
            accB[r] = pfma(h1, wB[1], accB[r]);
            accA[r] = pfma(h2, wA[2], accA[r]);
            accB[r] = pfma(h2, wB[2], accB[r]);
            accA[r] = pfma(h3, wA[3], accA[r]);
            accB[r] = pfma(h3, wB[3], accB[r]);
        }
    }

    float f0[8], f1v[8], f2v[8], f3[8];
    #pragma unroll
    for (int r = 0; r < 8; r++) {
        upk2(accA[r], f0[r], f1v[r]);
        upk2(accB[r], f2v[r], f3[r]);
    }

    // ---- score partials: sp[r] = sum_e Wh[row][c0+e] * (a1[c0+e], a2[c0+e]) ----
    ull apair[4];
    #pragma unroll
    for (int e = 0; e < 4; e++) apair[e] = pk2(a[c0 + e], a[FF + c0 + e]);
    ull sp[8];
    #pragma unroll
    for (int r = 0; r < 8; r++) {
        ull s = pfma(pk2(f0[r], f0[r]), apair[0], 0ULL);
        s = pfma(pk2(f1v[r], f1v[r]), apair[1], s);
        s = pfma(pk2(f2v[r], f2v[r]), apair[2], s);
        s = pfma(pk2(f3[r], f3[r]), apair[3], s);
        sp[r] = s;
    }

    __syncthreads();  // all threads done reading Ws before overlay
    #pragma unroll
    for (int r = 0; r < 8; r++)
        part[(r0 + r) * 32 + (tid & 31)] = sp[r];

    // ---- WhT global store (no smem involved) ----
    int b = blockIdx.x >> 5;
    int n0 = (blockIdx.x & 31) * 64;
    int bofs = (r0 & 31) >> 3;
    size_t grp32 = ((size_t)(n0 + (r0 & ~31))) >> 1;
    #pragma unroll
    for (int e = 0; e < 4; e++) {
        const float* fe = (e == 0) ? f0 : (e == 1) ? f1v : (e == 2) ? f2v : f3;
        uint32_t* dst = g_WhT32 + (((size_t)b * FF + c0 + e) * NN >> 1) + grp32 + bofs;
        #pragma unroll
        for (int s = 0; s < 4; s++)
            dst[4 * s] = pkhf(fe[2 * s], fe[2 * s + 1]);
    }

    __syncthreads();  // partials visible

    // ---- reduce 32 lanes per row; exps; store score tables ----
    if (tid < 64) {
        const ull* pr = part + tid * 32;
        float s1 = 0.f, s2 = 0.f;
        #pragma unroll
        for (int l = 0; l < 32; l++) {
            float lo, hi;
            upk2(pr[l], lo, hi);
            s1 += lo;
            s2 += hi;
        }
        int rowg = b * NN + n0 + tid;
        g_f1[rowg]  = s1;
        g_E1p[rowg] = expf(s1);
        g_E1n[rowg] = expf(0.2f * s1);
        int pj = b * NN + sigma32(n0 + tid);
        g_f2[pj]   = s2;
        g_E2h2[pj] = pkhf(expf(s2), expf(0.2f * s2));
    }
}

// ===================== k3: pipelined f16 mma masked-attention GEMM ===========
// 256 threads / 8 warps / 64 i-rows per CTA; 2 CTAs per SM; grid 256.
// smem (uint32 words): whts0@0(6144), whts1@6144, u0@12288(3072), u1@15360,
// ftab@18432(2048), ehtab@20480(2048), z@22528(64), bias@22592(128); tot 22720
#define K3_SMEM (22720 * 4)

// build masked-exp U for one row x 8 phys-j; byte mask (u64); emit 4 half2 words
__device__ __forceinline__ float build_u8(ull m, const float* ftab,
                                          const uint32_t* ehtab, int joff,
                                          float rf1, float rEp, float rEn,
                                          uint32_t* drow) {
    uint32_t pk[4];
    float zz = 0.f;
    #pragma unroll
    for (int g = 0; g < 2; g++) {
        float4 f = *(const float4*)&ftab[joff + g * 4];
        uint4 eh = *(const uint4*)&ehtab[joff + g * 4];
        float u[4];
        #pragma unroll
        for (int e = 0; e < 4; e++) {
            float2 pe = __half22float2(*reinterpret_cast<__half2*>(&(&eh.x)[e]));
            float s = rf1 + (&f.x)[e];
            float v = (s > 0.f) ? (rEp * pe.x) : (rEn * pe.y);
            u[e] = ((m >> (8 * (g * 4 + e))) & 0xFFu) ? v : 0.f;
        }
        pk[2 * g]     = pkhf(u[0], u[1]);
        pk[2 * g + 1] = pkhf(u[2], u[3]);
    }
    #pragma unroll
    for (int q = 0; q < 4; q++) {  // sum the fp16-rounded values
        float2 f2u = __half22float2(*reinterpret_cast<__half2*>(&pk[q]));
        zz += f2u.x + f2u.y;
    }
    *(uint4*)drow = make_uint4(pk[0], pk[1], pk[2], pk[3]);
    return zz;
}

__global__ __launch_bounds__(256, 2) void k3_main(const float* __restrict__ bias,
                                                  float* __restrict__ out) {
    extern __shared__ uint32_t smw[];
    uint32_t* whts[2] = { smw, smw + 6144 };
    uint32_t* u_s[2]  = { smw + 12288, smw + 15360 };
    float* ftab      = (float*)(smw + 18432);
    uint32_t* ehtab  = smw + 20480;
    float* z_s       = (float*)(smw + 22528);
    float* bias_s    = (float*)(smw + 22592);

    const int tid = threadIdx.x;
    const int b = blockIdx.x >> 5;
    const int i0 = (blockIdx.x & 31) * 64;
    const int bn = b * NN;

    // ---- per-CTA tables (whole permuted 2048-j range, loaded once) ----
    #pragma unroll
    for (int i = tid * 4; i < NN; i += 1024) {
        *(float4*)&ftab[i] = *(const float4*)&g_f2[bn + i];
        *(uint4*)&ehtab[i] = *(const uint4*)&g_E2h2[bn + i];
    }
    if (tid < 128) bias_s[tid] = bias[tid];

    // ---- builder identity: 2 rows, one 8-phys-j octet of the 64-j tile ----
    const int rp = tid >> 3;          // 0..31 (row pair)
    const int oct = tid & 7;          // 0..7
    const int rowa = 2 * rp;
    const float rf1a = g_f1[bn + i0 + rowa],   rf1b = g_f1[bn + i0 + rowa + 1];
    const float rEpa = g_E1p[bn + i0 + rowa],  rEpb = g_E1p[bn + i0 + rowa + 1];
    const float rEna = g_E1n[bn + i0 + rowa],  rEnb = g_E1n[bn + i0 + rowa + 1];
    const uint8_t* adja = g_adjP8 + (size_t)(i0 + rowa) * NN + oct * 8;
    const uint8_t* adjb = adja + NN;
    const int doffa = rowa * SRD32 + oct * 4;
    const int doffb = doffa + SRD32;

    // ---- WhT cp.async staging identity: row tid>>1, half tid&1 (16 words) ----
    const uint32_t* whp = g_WhT32 + (((size_t)b * FF + (tid >> 1)) * NN >> 1) + (tid & 1) * 16;
    const int sdo = (tid >> 1) * SRD32 + (tid & 1) * 16;
    const uint32_t wdst[2] = { smem_u32(whts[0]) + sdo * 4, smem_u32(whts[1]) + sdo * 4 };

    // ---- mma identity: 8 warps as 2(M) x 4(N); warp tile 32 x 32 ----
    const int lane = tid & 31, wid = tid >> 5;
    const int mg = wid >> 2, ng = wid & 3;
    const int l4 = lane >> 2, lm = lane & 3;

    float acc[2][4][4] = {};
    float z0 = 0.f, z1 = 0.f;
    ull ma, mb;

    __syncthreads();  // tables staged

    // ---- prologue: stage tile 0 ----
    #pragma unroll
    for (int ch = 0; ch < 4; ch++) cp_async16(wdst[0] + ch * 16, whp + ch * 4);
    asm volatile("cp.async.commit_group;");
    ma = *(const ull*)adja;
    mb = *(const ull*)adjb;
    z0 += build_u8(ma, ftab, ehtab, oct * 8, rf1a, rEpa, rEna, u_s[0] + doffa);
    z1 += build_u8(mb, ftab, ehtab, oct * 8, rf1b, rEpb, rEnb, u_s[0] + doffb);
    asm volatile("cp.async.wait_group 0;" ::: "memory");
    __syncthreads();

    for (int t = 0; t < 32; t++) {
        const int cur = t & 1, nxt = cur ^ 1;
        const int jb2 = (t + 1) * TJ;

        // ---- issue next tile's loads (async) ----
        if (t < 31) {
            #pragma unroll
            for (int ch = 0; ch < 4; ch++)
                cp_async16(wdst[nxt] + ch * 16, whp + (jb2 >> 1) + ch * 4);
            asm volatile("cp.async.commit_group;");
            ma = *(const ull*)(adja + jb2);
            mb = *(const ull*)(adjb + jb2);
        }

        // ---- mma(t): 2 k32 chunks x 2 k16 steps; conflict-free LDS.128 frags ----
        const uint32_t* wb = whts[cur];
        const uint32_t* ub = u_s[cur];
        #pragma unroll
        for (int ch = 0; ch < 2; ch++) {
            const int kc = ch * 16 + lm * 4;
            uint4 bv[4];
            #pragma unroll
            for (int ni = 0; ni < 4; ni++)
                bv[ni] = *(const uint4*)&wb[(ng * 32 + ni * 8 + l4) * SRD32 + kc];
            uint4 alo[2], ahi[2];
            #pragma unroll
            for (int mi = 0; mi < 2; mi++) {
                int row = mg * 32 + mi * 16 + l4;
                alo[mi] = *(const uint4*)&ub[row * SRD32 + kc];
                ahi[mi] = *(const uint4*)&ub[(row + 8) * SRD32 + kc];
            }
            #pragma unroll
            for (int mi = 0; mi < 2; mi++)    // k16 step 0
                #pragma unroll
                for (int ni = 0; ni < 4; ni++)
                    mma16(acc[mi][ni], alo[mi].x, ahi[mi].x, alo[mi].y, ahi[mi].y,
                          bv[ni].x, bv[ni].y);
            #pragma unroll
            for (int mi = 0; mi < 2; mi++)    // k16 step 1
                #pragma unroll
                for (int ni = 0; ni < 4; ni++)
                    mma16(acc[mi][ni], alo[mi].z, ahi[mi].z, alo[mi].w, ahi[mi].w,
                          bv[ni].z, bv[ni].w);
        }

        // ---- convert + store U(t+1) ----
        if (t < 31) {
            z0 += build_u8(ma, ftab, ehtab, jb2 + oct * 8, rf1a, rEpa, rEna, u_s[nxt] + doffa);
            z1 += build_u8(mb, ftab, ehtab, jb2 + oct * 8, rf1b, rEpb, rEnb, u_s[nxt] + doffb);
        }

        asm volatile("cp.async.wait_group 0;" ::: "memory");
        __syncthreads();
    }

    // ---- Z finalize: 8 octet-threads per row-pair are adjacent lanes ----
    #pragma unroll
    for (int o = 1; o < 8; o <<= 1) {
        z0 += __shfl_xor_sync(0xFFFFFFFFu, z0, o);
        z1 += __shfl_xor_sync(0xFFFFFFFFu, z1, o);
    }
    if (oct == 0) { z_s[rowa] = z0; z_s[rowa + 1] = z1; }
    __syncthreads();

    // ---- epilogue: 1/Z, +bias, ELU, store from fragments ----
    #pragma unroll
    for (int mi = 0; mi < 2; mi++) {
        const int r0 = mg * 32 + mi * 16 + l4;
        const float iz0 = 1.0f / z_s[r0];
        const float iz1 = 1.0f / z_s[r0 + 8];
        float* o0 = out + ((size_t)(bn + i0 + r0)) * FF;
        float* o1 = o0 + (size_t)8 * FF;
        #pragma unroll
        for (int ni = 0; ni < 4; ni++) {
            const int col = ng * 32 + ni * 8 + 2 * lm;
            const float b0 = bias_s[col], b1 = bias_s[col + 1];
            float x0 = acc[mi][ni][0] * iz0 + b0;
            float x1 = acc[mi][ni][1] * iz0 + b1;
            float x2 = acc[mi][ni][2] * iz1 + b0;
            float x3 = acc[mi][ni][3] * iz1 + b1;
            x0 = (x0 > 0.f) ? x0 : expm1f(x0);
            x1 = (x1 > 0.f) ? x1 : expm1f(x1);
            x2 = (x2 > 0.f) ? x2 : expm1f(x2);
            x3 = (x3 > 0.f) ? x3 : expm1f(x3);
            *(float2*)&o0[col] = make_float2(x0, x1);
            *(float2*)&o1[col] = make_float2(x2, x3);
        }
    }
}

// ============================== launch ==============================
extern "C" void kernel_launch(void* const* d_in, const int* in_sizes, int n_in,
                              void* d_out, int out_size) {
    const float* h    = (const float*)d_in[0];
    const float* adj  = (const float*)d_in[1];
    const float* W    = (const float*)d_in[2];
    const float* a    = (const float*)d_in[3];
    const float* bias = (const float*)d_in[4];
    float* out = (float*)d_out;

    const int smem1 = 65536 + 32768;
    cudaFuncSetAttribute(k1_gemm, cudaFuncAttributeMaxDynamicSharedMemorySize, smem1);
    cudaFuncSetAttribute(k3_main, cudaFuncAttributeMaxDynamicSharedMemorySize, K3_SMEM);

    k_adjP<<<NN * NN / 4 / 256, 256>>>(adj);
    k1_gemm<<<(BB * NN) / 64, 256, smem1>>>(h, W, a);
    k3_main<<<256, 256, K3_SMEM>>>(bias, out);
}